// round 1
// baseline (speedup 1.0000x reference)
#include <cuda_runtime.h>

// ---------------------------------------------------------------------------
// LinearSelfAttentionBlock: causal QK^T (NO softmax) => linear attention.
// attn_i = Q_i @ (sum_{j<=i} K_j^T outer V_j) / sqrt(H)
// Chunked prefix-state algorithm, O(B*N*d^2) instead of O(B*N^2*d).
// ---------------------------------------------------------------------------

#define TOK    128
#define HID    128
#define CH     128                 // chunk size (tokens)
#define NB     4
#define NSEQ   8192
#define NCB    (NSEQ / CH)         // 64 chunks per batch
#define NCHUNK (NB * NCB)          // 256 chunks total
#define PITCH  132                 // smem row pitch in floats (mult of 4, not mult of 32)

#define RSQRT_H 0.08838834764831845f   // 1/sqrt(128)

// Scratch (device globals: allocation-free rule)
__device__ float g_Q[NB * NSEQ * HID];   // 16 MB
__device__ float g_K[NB * NSEQ * HID];
__device__ float g_V[NB * NSEQ * TOK];
__device__ float g_S[NCHUNK * HID * TOK]; // per-chunk K^T V
__device__ float g_M[NCHUNK * HID * TOK]; // exclusive prefix of g_S per batch

// ---------------------------------------------------------------------------
// 128x128x128 fp32 microkernel. 256 threads, 8x8 register tile per thread.
// Thread (tx,ty): rows r = ty + 16*i, cols c = tx + 16*j.
// AT=0: A row-major [r][k];  AT=1: A stored [k][r] (i.e. computes A^T @ ...)
// BT=0: B row-major [k][c];  BT=1: B stored [c][k] (i.e. ... @ B^T)
// ---------------------------------------------------------------------------
template <int AT, int BT>
__device__ __forceinline__ void mm128(const float* __restrict__ As,
                                      const float* __restrict__ Bs,
                                      float acc[8][8], int tx, int ty) {
#pragma unroll 4
    for (int k = 0; k < 128; k++) {
        float a[8], b[8];
#pragma unroll
        for (int i = 0; i < 8; i++)
            a[i] = AT ? As[k * PITCH + ty + 16 * i]
                      : As[(ty + 16 * i) * PITCH + k];
#pragma unroll
        for (int j = 0; j < 8; j++)
            b[j] = BT ? Bs[(tx + 16 * j) * PITCH + k]
                      : Bs[k * PITCH + tx + 16 * j];
#pragma unroll
        for (int i = 0; i < 8; i++)
#pragma unroll
            for (int j = 0; j < 8; j++)
                acc[i][j] = fmaf(a[i], b[j], acc[i][j]);
    }
}

__device__ __forceinline__ void zero_acc(float acc[8][8]) {
#pragma unroll
    for (int i = 0; i < 8; i++)
#pragma unroll
        for (int j = 0; j < 8; j++) acc[i][j] = 0.0f;
}

// Copy a 128x128 fp32 row-major gmem tile into smem with PITCH rows.
__device__ __forceinline__ void load_tile(float* dst, const float* __restrict__ src,
                                          int tid) {
#pragma unroll
    for (int it = 0; it < 16; it++) {
        int idx = tid + it * 256;        // 4096 float4 loads total
        int r   = idx >> 5;              // 32 float4 per row
        int c4  = idx & 31;
        float4 v = ((const float4*)src)[idx];
        *(float4*)&dst[r * PITCH + c4 * 4] = v;
    }
}

// ---------------------------------------------------------------------------
// Kernel 1: LN1 + Q/K/V projections, one CTA per 128-token chunk.
// ---------------------------------------------------------------------------
extern "C" __global__ void __launch_bounds__(256, 1)
k_ln1_qkv(const float* __restrict__ tokens,
          const float* __restrict__ Wq, const float* __restrict__ Wk,
          const float* __restrict__ Wv,
          const float* __restrict__ g1, const float* __restrict__ b1) {
    extern __shared__ float smem[];
    float* sTn = smem;                 // 128 * PITCH
    float* sW  = smem + 128 * PITCH;

    int tid  = threadIdx.x;
    int tx   = tid & 15, ty = tid >> 4;
    int wid  = tid >> 5, lane = tid & 31;
    int base = blockIdx.x * CH;        // global token index base

    // LN1: one warp per row, float4 per lane
    for (int r = wid; r < CH; r += 8) {
        float4 v = ((const float4*)(tokens + (size_t)(base + r) * TOK))[lane];
        float s  = v.x + v.y + v.z + v.w;
        float s2 = v.x * v.x + v.y * v.y + v.z * v.z + v.w * v.w;
#pragma unroll
        for (int o = 16; o; o >>= 1) {
            s  += __shfl_xor_sync(0xffffffffu, s, o);
            s2 += __shfl_xor_sync(0xffffffffu, s2, o);
        }
        float mu  = s * (1.0f / TOK);
        float var = fmaxf(s2 * (1.0f / TOK) - mu * mu, 0.0f);
        float inv = rsqrtf(var + 1e-5f);
        float4 gg = ((const float4*)g1)[lane];
        float4 bb = ((const float4*)b1)[lane];
        float4 o4;
        o4.x = (v.x - mu) * inv * gg.x + bb.x;
        o4.y = (v.y - mu) * inv * gg.y + bb.y;
        o4.z = (v.z - mu) * inv * gg.z + bb.z;
        o4.w = (v.w - mu) * inv * gg.w + bb.w;
        *(float4*)&sTn[r * PITCH + lane * 4] = o4;
    }

    float acc[8][8];
    const float* Ws[3] = {Wq, Wk, Wv};
    float* outs[3] = {g_Q, g_K, g_V};

    for (int m = 0; m < 3; m++) {
        if (m > 0) __syncthreads();       // everyone done reading sW before overwrite
        load_tile(sW, Ws[m], tid);
        __syncthreads();
        zero_acc(acc);
        mm128<0, 1>(sTn, sW, acc, tx, ty);     // tn @ W^T  (both K-major)
        float* dst = outs[m];
#pragma unroll
        for (int i = 0; i < 8; i++) {
            int r = ty + 16 * i;
#pragma unroll
            for (int j = 0; j < 8; j++)
                dst[(base + r) * HID + tx + 16 * j] = acc[i][j];
        }
    }
}

// ---------------------------------------------------------------------------
// Kernel 2: per-chunk state S_c = K_c^T @ V_c  (H x T)
// ---------------------------------------------------------------------------
extern "C" __global__ void __launch_bounds__(256, 1)
k_state() {
    extern __shared__ float smem[];
    float* sK = smem;
    float* sV = smem + 128 * PITCH;
    int tid = threadIdx.x, tx = tid & 15, ty = tid >> 4;
    int base = blockIdx.x * CH;

    load_tile(sK, g_K + base * HID, tid);
    load_tile(sV, g_V + base * TOK, tid);
    __syncthreads();

    float acc[8][8];
    zero_acc(acc);
    mm128<1, 0>(sK, sV, acc, tx, ty);   // S[h][t] = sum_k K[k][h] * V[k][t]
    float* dst = g_S + blockIdx.x * HID * TOK;
#pragma unroll
    for (int i = 0; i < 8; i++)
#pragma unroll
        for (int j = 0; j < 8; j++)
            dst[(ty + 16 * i) * TOK + tx + 16 * j] = acc[i][j];
}

// ---------------------------------------------------------------------------
// Kernel 3: exclusive prefix-sum of S over chunks (per batch, per element).
// 65536 threads, each owns one (b, h, t) element, scans 64 chunks.
// ---------------------------------------------------------------------------
extern "C" __global__ void __launch_bounds__(256)
k_prefix() {
    int t = blockIdx.x * 256 + threadIdx.x;   // 0..65535
    int b = t >> 14;                          // / 16384
    int e = t & 16383;
    float s = 0.0f;
    for (int c = 0; c < NCB; c++) {
        int idx = (b * NCB + c) * (HID * TOK) + e;
        g_M[idx] = s;
        s += g_S[idx];
    }
}

// ---------------------------------------------------------------------------
// Kernel 4: per chunk: P = tril(Q K^T); attn = (Q@M + P@V)/sqrt(H);
//           out = LN2(tokens + 0.1 * attn @ Wo^T)
// ---------------------------------------------------------------------------
extern "C" __global__ void __launch_bounds__(256, 1)
k_attn_out(const float* __restrict__ tokens,
           const float* __restrict__ Wo,
           const float* __restrict__ g2, const float* __restrict__ b2,
           float* __restrict__ out) {
    extern __shared__ float smem[];
    float* bufA = smem;                       // Q, later attn
    float* bufB = smem + 128 * PITCH;         // K, M, V, Wo
    float* bufP = smem + 2 * 128 * PITCH;     // P, later pre-LN residual

    int tid  = threadIdx.x;
    int tx   = tid & 15, ty = tid >> 4;
    int wid  = tid >> 5, lane = tid & 31;
    int cid  = blockIdx.x;
    int base = cid * CH;

    load_tile(bufA, g_Q + base * HID, tid);
    load_tile(bufB, g_K + base * HID, tid);
    __syncthreads();

    float acc[8][8];

    // P = Q @ K^T, causal mask within chunk
    zero_acc(acc);
    mm128<0, 1>(bufA, bufB, acc, tx, ty);
#pragma unroll
    for (int i = 0; i < 8; i++) {
        int r = ty + 16 * i;
#pragma unroll
        for (int j = 0; j < 8; j++) {
            int c = tx + 16 * j;
            bufP[r * PITCH + c] = (c <= r) ? acc[i][j] : 0.0f;
        }
    }
    __syncthreads();                          // done reading K, P visible

    // acc = Q @ M  (M row-major [h][t])
    load_tile(bufB, g_M + cid * (HID * TOK), tid);
    __syncthreads();
    zero_acc(acc);
    mm128<0, 0>(bufA, bufB, acc, tx, ty);
    __syncthreads();                          // done reading M

    // acc += P @ V
    load_tile(bufB, g_V + base * TOK, tid);
    __syncthreads();
    mm128<0, 0>(bufP, bufB, acc, tx, ty);
    __syncthreads();                          // done reading P, V, (Q long done)

    // attn -> bufA (overwrite Q); load Wo
#pragma unroll
    for (int i = 0; i < 8; i++)
#pragma unroll
        for (int j = 0; j < 8; j++)
            bufA[(ty + 16 * i) * PITCH + tx + 16 * j] = acc[i][j] * RSQRT_H;
    load_tile(bufB, Wo, tid);
    __syncthreads();

    // out = attn @ Wo^T
    zero_acc(acc);
    mm128<0, 1>(bufA, bufB, acc, tx, ty);

    // residual: x + 0.1 * proj  -> bufP
#pragma unroll
    for (int i = 0; i < 8; i++) {
        int r = ty + 16 * i;
#pragma unroll
        for (int j = 0; j < 8; j++) {
            int c = tx + 16 * j;
            float x = tokens[(size_t)(base + r) * TOK + c];
            bufP[r * PITCH + c] = x + 0.1f * acc[i][j];
        }
    }
    __syncthreads();

    // LN2: one warp per row
    for (int r = wid; r < CH; r += 8) {
        float4 v = *(const float4*)&bufP[r * PITCH + lane * 4];
        float s  = v.x + v.y + v.z + v.w;
        float s2 = v.x * v.x + v.y * v.y + v.z * v.z + v.w * v.w;
#pragma unroll
        for (int o = 16; o; o >>= 1) {
            s  += __shfl_xor_sync(0xffffffffu, s, o);
            s2 += __shfl_xor_sync(0xffffffffu, s2, o);
        }
        float mu  = s * (1.0f / TOK);
        float var = fmaxf(s2 * (1.0f / TOK) - mu * mu, 0.0f);
        float inv = rsqrtf(var + 1e-5f);
        float4 gg = ((const float4*)g2)[lane];
        float4 bb = ((const float4*)b2)[lane];
        float4 o4;
        o4.x = (v.x - mu) * inv * gg.x + bb.x;
        o4.y = (v.y - mu) * inv * gg.y + bb.y;
        o4.z = (v.z - mu) * inv * gg.z + bb.z;
        o4.w = (v.w - mu) * inv * gg.w + bb.w;
        ((float4*)(out + (size_t)(base + r) * TOK))[lane] = o4;
    }
}

// ---------------------------------------------------------------------------
extern "C" void kernel_launch(void* const* d_in, const int* in_sizes, int n_in,
                              void* d_out, int out_size) {
    const float* tokens = (const float*)d_in[0];
    const float* Wq = (const float*)d_in[1];
    const float* Wk = (const float*)d_in[2];
    const float* Wv = (const float*)d_in[3];
    const float* Wo = (const float*)d_in[4];
    const float* g1 = (const float*)d_in[5];
    const float* b1 = (const float*)d_in[6];
    const float* g2 = (const float*)d_in[7];
    const float* b2 = (const float*)d_in[8];
    float* out = (float*)d_out;

    const int sm2 = 2 * 128 * PITCH * (int)sizeof(float);   // 135168
    const int sm3 = 3 * 128 * PITCH * (int)sizeof(float);   // 202752
    cudaFuncSetAttribute(k_ln1_qkv,  cudaFuncAttributeMaxDynamicSharedMemorySize, sm2);
    cudaFuncSetAttribute(k_state,    cudaFuncAttributeMaxDynamicSharedMemorySize, sm2);
    cudaFuncSetAttribute(k_attn_out, cudaFuncAttributeMaxDynamicSharedMemorySize, sm3);

    k_ln1_qkv<<<NCHUNK, 256, sm2>>>(tokens, Wq, Wk, Wv, g1, b1);
    k_state<<<NCHUNK, 256, sm2>>>();
    k_prefix<<<NCHUNK, 256>>>();
    k_attn_out<<<NCHUNK, 256, sm3>>>(tokens, Wo, g2, b2, out);
}

// round 3
// speedup vs baseline: 3.0431x; 3.0431x over previous
#include <cuda_runtime.h>
#include <cuda_bf16.h>
#include <stdint.h>

// ---------------------------------------------------------------------------
// Linear attention (causal QK^T, NO softmax) via chunked prefix-state.
// All 128x128x128 matmuls on mma.sync.m16n8k16 bf16 (compiles on plain sm_103
// target -- tcgen05 is arch-specific and the harness emits a compute_103 pass).
// ---------------------------------------------------------------------------

#define NB      4
#define NSEQ    8192
#define CH      128
#define NCB     (NSEQ / CH)        // 64
#define NCHUNK  (NB * NCB)         // 256
#define TILE    16384              // 128*128
#define RSQRT_H 0.08838834764831845f

// Scratch (device globals: allocation-free rule)
__device__ __nv_bfloat16 g_Q [NCHUNK * TILE];
__device__ __nv_bfloat16 g_K [NCHUNK * TILE];
__device__ __nv_bfloat16 g_Kt[NCHUNK * TILE];
__device__ __nv_bfloat16 g_Vt[NCHUNK * TILE];
__device__ float         g_S [NCHUNK * TILE];
__device__ __nv_bfloat16 g_Mt[NCHUNK * TILE];

// =========================== helpers =======================================
__device__ __forceinline__ uint32_t smem_u32(const void* p) {
    uint32_t a;
    asm("{ .reg .u64 t; cvta.to.shared.u64 t, %1; cvt.u32.u64 %0, t; }"
        : "=r"(a) : "l"(p));
    return a;
}

// Swizzled byte offset inside a 128x128 bf16 tile (256B rows).
// colg = 8-element (16B) group index, 0..15.  XOR with row&7 -> ldmatrix
// reads of 8 consecutive rows at one colg hit 8 distinct 16B banksets.
__device__ __forceinline__ uint32_t swz(int row, int colg) {
    return (uint32_t)(row * 256) + (uint32_t)(((colg ^ (row & 7)) << 4));
}

__device__ __forceinline__ uint32_t pack_bf16(float lo, float hi) {
    __nv_bfloat162 h;
    h.x = __float2bfloat16(lo);
    h.y = __float2bfloat16(hi);
    return *reinterpret_cast<uint32_t*>(&h);
}

__device__ __forceinline__ void ldm4(uint32_t addr, uint32_t r[4]) {
    asm volatile("ldmatrix.sync.aligned.m8n8.x4.shared.b16 {%0,%1,%2,%3}, [%4];"
                 : "=r"(r[0]), "=r"(r[1]), "=r"(r[2]), "=r"(r[3]) : "r"(addr));
}

__device__ __forceinline__ void mma16816(float* c, const uint32_t a[4],
                                         uint32_t b0, uint32_t b1) {
    asm volatile(
        "mma.sync.aligned.m16n8k16.row.col.f32.bf16.bf16.f32 "
        "{%0,%1,%2,%3},{%4,%5,%6,%7},{%8,%9},{%0,%1,%2,%3};"
        : "+f"(c[0]), "+f"(c[1]), "+f"(c[2]), "+f"(c[3])
        : "r"(a[0]), "r"(a[1]), "r"(a[2]), "r"(a[3]), "r"(b0), "r"(b1));
}

// 128x128x128: C[m][n] (+)= A[m][k] * B[n][k]^T, swizzled bf16 smem tiles.
// 8 warps: warp w owns rows mo=(w&3)*32, cols no=(w>>2)*64. acc[2][8][4].
__device__ __forceinline__ void mm_ss(uint32_t sa, uint32_t sb,
                                      float acc[2][8][4], int lane, int mo, int no) {
    int ra = lane & 15;                          // A ldmatrix row-in-tile
    int rb = ((lane >> 4) << 3) + (lane & 7);    // B ldmatrix row-in-tile
    int ca = lane >> 4;                          // A k-halfblock
    int cb = (lane >> 3) & 1;                    // B k-halfblock
#pragma unroll
    for (int kk = 0; kk < 8; kk++) {
        uint32_t a[2][4], b[4][4];
#pragma unroll
        for (int mt = 0; mt < 2; mt++)
            ldm4(sa + swz(mo + mt * 16 + ra, kk * 2 + ca), a[mt]);
#pragma unroll
        for (int nt2 = 0; nt2 < 4; nt2++)
            ldm4(sb + swz(no + nt2 * 16 + rb, kk * 2 + cb), b[nt2]);
#pragma unroll
        for (int mt = 0; mt < 2; mt++)
#pragma unroll
            for (int nt = 0; nt < 8; nt++)
                mma16816(acc[mt][nt], a[mt],
                         b[nt >> 1][(nt & 1) * 2], b[nt >> 1][(nt & 1) * 2 + 1]);
    }
}

__device__ __forceinline__ void zacc(float acc[2][8][4]) {
#pragma unroll
    for (int mt = 0; mt < 2; mt++)
#pragma unroll
        for (int nt = 0; nt < 8; nt++)
#pragma unroll
            for (int j = 0; j < 4; j++) acc[mt][nt][j] = 0.0f;
}

// fp32 row-major 128x128 gmem -> bf16 swizzled smem tile (256 threads)
__device__ __forceinline__ void load_w(char* dst, const float* __restrict__ W, int tid) {
#pragma unroll
    for (int i = 0; i < 8; i++) {
        int idx = tid + i * 256;                 // 2048 16B-granules
        int row = idx >> 4, g = idx & 15;
        const float4* p = (const float4*)(W + row * 128 + g * 8);
        float4 v0 = p[0], v1 = p[1];
        uint4 o;
        o.x = pack_bf16(v0.x, v0.y);  o.y = pack_bf16(v0.z, v0.w);
        o.z = pack_bf16(v1.x, v1.y);  o.w = pack_bf16(v1.z, v1.w);
        *(uint4*)(dst + swz(row, g)) = o;
    }
}

// bf16 row-major 128x128 gmem -> swizzled smem tile
__device__ __forceinline__ void load_t(char* dst, const __nv_bfloat16* __restrict__ src, int tid) {
#pragma unroll
    for (int i = 0; i < 8; i++) {
        int idx = tid + i * 256;
        int row = idx >> 4, g = idx & 15;
        *(uint4*)(dst + swz(row, g)) = ((const uint4*)src)[idx];
    }
}

// accum -> bf16 row-major gmem tile
__device__ __forceinline__ void store_bf16(float acc[2][8][4],
                                           __nv_bfloat16* __restrict__ dst,
                                           int lane, int mo, int no) {
    int g = lane >> 2, t = lane & 3;
#pragma unroll
    for (int mt = 0; mt < 2; mt++)
#pragma unroll
        for (int nt = 0; nt < 8; nt++) {
            int col = no + nt * 8 + 2 * t;
            int r0 = mo + mt * 16 + g;
            *(uint32_t*)(dst + r0 * 128 + col)       = pack_bf16(acc[mt][nt][0], acc[mt][nt][1]);
            *(uint32_t*)(dst + (r0 + 8) * 128 + col) = pack_bf16(acc[mt][nt][2], acc[mt][nt][3]);
        }
}

// ===========================================================================
// Kernel 1: LN1 + {Q, K, Kt, Vt}.  Transposes come free by swapping operands.
// smem: Tn@0, Wq@32K, Wk@64K, Wv@96K
// ===========================================================================
#define K1_SMEM (4 * 32768)

extern "C" __global__ void __launch_bounds__(256, 1)
k_ln1_qkv(const float* __restrict__ tokens,
          const float* __restrict__ Wq, const float* __restrict__ Wk,
          const float* __restrict__ Wv,
          const float* __restrict__ g1, const float* __restrict__ b1) {
    extern __shared__ char smem[];
    char* sT = smem;
    int tid = threadIdx.x, wid = tid >> 5, lane = tid & 31;
    int mo = (wid & 3) * 32, no = (wid >> 2) * 64;
    int cid = blockIdx.x, base = cid * CH;

    // LN1 -> swizzled bf16 tile
    for (int r = wid; r < CH; r += 8) {
        float4 v = ((const float4*)(tokens + (size_t)(base + r) * 128))[lane];
        float s  = v.x + v.y + v.z + v.w;
        float s2 = v.x * v.x + v.y * v.y + v.z * v.z + v.w * v.w;
#pragma unroll
        for (int o = 16; o; o >>= 1) {
            s  += __shfl_xor_sync(0xffffffffu, s, o);
            s2 += __shfl_xor_sync(0xffffffffu, s2, o);
        }
        float mu  = s * (1.0f / 128.0f);
        float var = fmaxf(s2 * (1.0f / 128.0f) - mu * mu, 0.0f);
        float inv = rsqrtf(var + 1e-5f);
        float4 gg = ((const float4*)g1)[lane];
        float4 bb = ((const float4*)b1)[lane];
        float o0 = (v.x - mu) * inv * gg.x + bb.x;
        float o1 = (v.y - mu) * inv * gg.y + bb.y;
        float o2 = (v.z - mu) * inv * gg.z + bb.z;
        float o3 = (v.w - mu) * inv * gg.w + bb.w;
        uint32_t off = swz(r, lane >> 1) + (lane & 1) * 8;
        *(uint32_t*)(sT + off)     = pack_bf16(o0, o1);
        *(uint32_t*)(sT + off + 4) = pack_bf16(o2, o3);
    }
    load_w(smem + 32768, Wq, tid);
    load_w(smem + 65536, Wk, tid);
    load_w(smem + 98304, Wv, tid);
    __syncthreads();

    uint32_t sb = smem_u32(smem);
    float acc[2][8][4];

    zacc(acc); mm_ss(sb, sb + 32768, acc, lane, mo, no);           // Q  = tn @ Wq^T
    store_bf16(acc, g_Q + (size_t)cid * TILE, lane, mo, no);
    zacc(acc); mm_ss(sb, sb + 65536, acc, lane, mo, no);           // K  = tn @ Wk^T
    store_bf16(acc, g_K + (size_t)cid * TILE, lane, mo, no);
    zacc(acc); mm_ss(sb + 65536, sb, acc, lane, mo, no);           // Kt = Wk @ tn^T
    store_bf16(acc, g_Kt + (size_t)cid * TILE, lane, mo, no);
    zacc(acc); mm_ss(sb + 98304, sb, acc, lane, mo, no);           // Vt = Wv @ tn^T
    store_bf16(acc, g_Vt + (size_t)cid * TILE, lane, mo, no);
}

// ===========================================================================
// Kernel 2: St[v][h] = Vt @ Kt^T (contract over local token j) -> fp32 g_S
// ===========================================================================
#define K2_SMEM (2 * 32768)

extern "C" __global__ void __launch_bounds__(256, 1)
k_state() {
    extern __shared__ char smem[];
    int tid = threadIdx.x, wid = tid >> 5, lane = tid & 31;
    int mo = (wid & 3) * 32, no = (wid >> 2) * 64;
    int cid = blockIdx.x;

    load_t(smem,         g_Vt + (size_t)cid * TILE, tid);
    load_t(smem + 32768, g_Kt + (size_t)cid * TILE, tid);
    __syncthreads();

    uint32_t sb = smem_u32(smem);
    float acc[2][8][4];
    zacc(acc);
    mm_ss(sb, sb + 32768, acc, lane, mo, no);

    float* dst = g_S + (size_t)cid * TILE;
    int g = lane >> 2, t = lane & 3;
#pragma unroll
    for (int mt = 0; mt < 2; mt++)
#pragma unroll
        for (int nt = 0; nt < 8; nt++) {
            int col = no + nt * 8 + 2 * t;
            int r0 = mo + mt * 16 + g;
            *(float2*)(dst + r0 * 128 + col)       = make_float2(acc[mt][nt][0], acc[mt][nt][1]);
            *(float2*)(dst + (r0 + 8) * 128 + col) = make_float2(acc[mt][nt][2], acc[mt][nt][3]);
        }
}

// ===========================================================================
// Kernel 3: per-element exclusive prefix over chunks -> bf16 g_Mt
// ===========================================================================
extern "C" __global__ void __launch_bounds__(256)
k_prefix() {
    int t = blockIdx.x * 256 + threadIdx.x;   // 65536 threads
    int b = t >> 14, e = t & 16383;
    const float* S = g_S + (size_t)b * NCB * TILE + e;
    __nv_bfloat16* M = g_Mt + (size_t)b * NCB * TILE + e;
    float s = 0.0f;
    for (int c = 0; c < NCB; c++) {
        M[(size_t)c * TILE] = __float2bfloat16(s);
        s += S[(size_t)c * TILE];
    }
}

// ===========================================================================
// Kernel 4: scores = tril(Q K^T); attn = Q@Mt^T + P@Vt^T;
//           out = LN2(x + 0.1 * attn @ Wo^T)
// smem: Q/attn@0, K->Wo@32K, Mt->Vt@64K, P@96K, res fp32 @128K (pitch 132)
// ===========================================================================
#define K4_SMEM (4 * 32768 + 128 * 132 * 4)

extern "C" __global__ void __launch_bounds__(256, 1)
k_attn_out(const float* __restrict__ tokens,
           const float* __restrict__ Wo,
           const float* __restrict__ g2, const float* __restrict__ b2,
           float* __restrict__ out) {
    extern __shared__ char smem[];
    char*  sQ  = smem;
    char*  sP  = smem + 98304;
    float* res = (float*)(smem + 131072);
    int tid = threadIdx.x, wid = tid >> 5, lane = tid & 31;
    int mo = (wid & 3) * 32, no = (wid >> 2) * 64;
    int g = lane >> 2, t = lane & 3;
    int cid = blockIdx.x, base = cid * CH;

    load_t(sQ,           g_Q  + (size_t)cid * TILE, tid);
    load_t(smem + 32768, g_K  + (size_t)cid * TILE, tid);
    load_t(smem + 65536, g_Mt + (size_t)cid * TILE, tid);
#pragma unroll
    for (int i = 0; i < 16; i++) {                    // tokens -> res stage
        int idx = tid + i * 256;
        int rr = idx >> 5, c4 = idx & 31;
        float4 v = ((const float4*)(tokens + (size_t)base * 128))[idx];
        *(float4*)&res[rr * 132 + c4 * 4] = v;
    }
    __syncthreads();

    uint32_t sb = smem_u32(smem);
    float acc_s[2][8][4], acc_a[2][8][4];
    zacc(acc_s); zacc(acc_a);
    mm_ss(sb, sb + 32768, acc_s, lane, mo, no);       // scores = Q @ K^T
    mm_ss(sb, sb + 65536, acc_a, lane, mo, no);       // attn   = Q @ Mt^T
    __syncthreads();                                  // everyone done reading K/Mt

    // masked P -> sP (bf16 swizzled); reload B buffers
#pragma unroll
    for (int mt = 0; mt < 2; mt++)
#pragma unroll
        for (int nt = 0; nt < 8; nt++) {
            int col = no + nt * 8 + 2 * t;
            int r0 = mo + mt * 16 + g, r1 = r0 + 8;
            float v0 = (col     <= r0) ? acc_s[mt][nt][0] : 0.0f;
            float v1 = (col + 1 <= r0) ? acc_s[mt][nt][1] : 0.0f;
            float v2 = (col     <= r1) ? acc_s[mt][nt][2] : 0.0f;
            float v3 = (col + 1 <= r1) ? acc_s[mt][nt][3] : 0.0f;
            *(uint32_t*)(sP + swz(r0, col >> 3) + (col & 7) * 2) = pack_bf16(v0, v1);
            *(uint32_t*)(sP + swz(r1, col >> 3) + (col & 7) * 2) = pack_bf16(v2, v3);
        }
    load_t(smem + 65536, g_Vt + (size_t)cid * TILE, tid);
    load_w(smem + 32768, Wo, tid);
    __syncthreads();

    mm_ss(sb + 98304, sb + 65536, acc_a, lane, mo, no);   // attn += P @ Vt^T

    // attn * 1/sqrt(H) -> bf16 swizzled into sQ
#pragma unroll
    for (int mt = 0; mt < 2; mt++)
#pragma unroll
        for (int nt = 0; nt < 8; nt++) {
            int col = no + nt * 8 + 2 * t;
            int r0 = mo + mt * 16 + g, r1 = r0 + 8;
            *(uint32_t*)(sQ + swz(r0, col >> 3) + (col & 7) * 2) =
                pack_bf16(acc_a[mt][nt][0] * RSQRT_H, acc_a[mt][nt][1] * RSQRT_H);
            *(uint32_t*)(sQ + swz(r1, col >> 3) + (col & 7) * 2) =
                pack_bf16(acc_a[mt][nt][2] * RSQRT_H, acc_a[mt][nt][3] * RSQRT_H);
        }
    __syncthreads();

    zacc(acc_s);
    mm_ss(sb, sb + 32768, acc_s, lane, mo, no);           // proj = attn @ Wo^T

    // residual into res stage
#pragma unroll
    for (int mt = 0; mt < 2; mt++)
#pragma unroll
        for (int nt = 0; nt < 8; nt++) {
            int col = no + nt * 8 + 2 * t;
            int r0 = mo + mt * 16 + g, r1 = r0 + 8;
            res[r0 * 132 + col]     += 0.1f * acc_s[mt][nt][0];
            res[r0 * 132 + col + 1] += 0.1f * acc_s[mt][nt][1];
            res[r1 * 132 + col]     += 0.1f * acc_s[mt][nt][2];
            res[r1 * 132 + col + 1] += 0.1f * acc_s[mt][nt][3];
        }
    __syncthreads();

    // LN2 per row -> out
    for (int r = wid; r < CH; r += 8) {
        float4 v = *(const float4*)&res[r * 132 + lane * 4];
        float s  = v.x + v.y + v.z + v.w;
        float s2 = v.x * v.x + v.y * v.y + v.z * v.z + v.w * v.w;
#pragma unroll
        for (int o = 16; o; o >>= 1) {
            s  += __shfl_xor_sync(0xffffffffu, s, o);
            s2 += __shfl_xor_sync(0xffffffffu, s2, o);
        }
        float mu  = s * (1.0f / 128.0f);
        float var = fmaxf(s2 * (1.0f / 128.0f) - mu * mu, 0.0f);
        float inv = rsqrtf(var + 1e-5f);
        float4 gg = ((const float4*)g2)[lane];
        float4 bb = ((const float4*)b2)[lane];
        float4 o4;
        o4.x = (v.x - mu) * inv * gg.x + bb.x;
        o4.y = (v.y - mu) * inv * gg.y + bb.y;
        o4.z = (v.z - mu) * inv * gg.z + bb.z;
        o4.w = (v.w - mu) * inv * gg.w + bb.w;
        ((float4*)(out + (size_t)(base + r) * 128))[lane] = o4;
    }
}

// ===========================================================================
extern "C" void kernel_launch(void* const* d_in, const int* in_sizes, int n_in,
                              void* d_out, int out_size) {
    const float* tokens = (const float*)d_in[0];
    const float* Wq = (const float*)d_in[1];
    const float* Wk = (const float*)d_in[2];
    const float* Wv = (const float*)d_in[3];
    const float* Wo = (const float*)d_in[4];
    const float* g1 = (const float*)d_in[5];
    const float* b1 = (const float*)d_in[6];
    const float* g2 = (const float*)d_in[7];
    const float* b2 = (const float*)d_in[8];
    float* out = (float*)d_out;

    cudaFuncSetAttribute(k_ln1_qkv,  cudaFuncAttributeMaxDynamicSharedMemorySize, K1_SMEM);
    cudaFuncSetAttribute(k_state,    cudaFuncAttributeMaxDynamicSharedMemorySize, K2_SMEM);
    cudaFuncSetAttribute(k_attn_out, cudaFuncAttributeMaxDynamicSharedMemorySize, K4_SMEM);

    k_ln1_qkv<<<NCHUNK, 256, K1_SMEM>>>(tokens, Wq, Wk, Wv, g1, b1);
    k_state<<<NCHUNK, 256, K2_SMEM>>>();
    k_prefix<<<NCHUNK, 256>>>();
    k_attn_out<<<NCHUNK, 256, K4_SMEM>>>(tokens, Wo, g2, b2, out);
}

// round 4
// speedup vs baseline: 3.4074x; 1.1197x over previous
#include <cuda_runtime.h>
#include <cuda_bf16.h>
#include <stdint.h>

// ---------------------------------------------------------------------------
// Linear attention (causal QK^T, NO softmax) via chunked prefix-state.
// mma.sync.m16n8k16 bf16 everywhere. 3 kernels:
//   K1: LN1 + Q,K,Kt,Vt projections + fused per-chunk state St = Vt@Kt^T
//   K3: exclusive prefix scan of St over chunks -> Mt (bf16)
//   K4: scores=tril(QK^T); attn = Q@Mt^T + P@Vt^T; out = LN2(x + 0.1*attn@Wo^T)
// All big kernels: 96KB smem, <=128 regs -> 2 CTAs/SM (was 1).
// ---------------------------------------------------------------------------

#define NB      4
#define NSEQ    8192
#define CH      128
#define NCB     (NSEQ / CH)        // 64
#define NCHUNK  (NB * NCB)         // 256
#define TILE    16384              // 128*128
#define RSQRT_H 0.08838834764831845f

// Scratch (device globals: allocation-free rule)
__device__ __nv_bfloat16 g_Q [NCHUNK * TILE];
__device__ __nv_bfloat16 g_K [NCHUNK * TILE];
__device__ __nv_bfloat16 g_Vt[NCHUNK * TILE];
__device__ float         g_S [NCHUNK * TILE];
__device__ __nv_bfloat16 g_Mt[NCHUNK * TILE];

// =========================== helpers =======================================
__device__ __forceinline__ uint32_t smem_u32(const void* p) {
    uint32_t a;
    asm("{ .reg .u64 t; cvta.to.shared.u64 t, %1; cvt.u32.u64 %0, t; }"
        : "=r"(a) : "l"(p));
    return a;
}

// Swizzled byte offset inside a 128x128 bf16 tile (256B rows).
__device__ __forceinline__ uint32_t swz(int row, int colg) {
    return (uint32_t)(row * 256) + (uint32_t)(((colg ^ (row & 7)) << 4));
}

__device__ __forceinline__ uint32_t pack_bf16(float lo, float hi) {
    __nv_bfloat162 h;
    h.x = __float2bfloat16(lo);
    h.y = __float2bfloat16(hi);
    return *reinterpret_cast<uint32_t*>(&h);
}

__device__ __forceinline__ void ldm4(uint32_t addr, uint32_t r[4]) {
    asm volatile("ldmatrix.sync.aligned.m8n8.x4.shared.b16 {%0,%1,%2,%3}, [%4];"
                 : "=r"(r[0]), "=r"(r[1]), "=r"(r[2]), "=r"(r[3]) : "r"(addr));
}

__device__ __forceinline__ void mma16816(float* c, const uint32_t a[4],
                                         uint32_t b0, uint32_t b1) {
    asm volatile(
        "mma.sync.aligned.m16n8k16.row.col.f32.bf16.bf16.f32 "
        "{%0,%1,%2,%3},{%4,%5,%6,%7},{%8,%9},{%0,%1,%2,%3};"
        : "+f"(c[0]), "+f"(c[1]), "+f"(c[2]), "+f"(c[3])
        : "r"(a[0]), "r"(a[1]), "r"(a[2]), "r"(a[3]), "r"(b0), "r"(b1));
}

// 128x128x128: C[m][n] += A[m][k] * B[n][k]^T, swizzled bf16 smem tiles.
// 8 warps: warp w owns rows mo=(w&3)*32, cols no=(w>>2)*64. acc[2][8][4].
__device__ __forceinline__ void mm_ss(uint32_t sa, uint32_t sb,
                                      float acc[2][8][4], int lane, int mo, int no) {
    int ra = lane & 15;
    int rb = ((lane >> 4) << 3) + (lane & 7);
    int ca = lane >> 4;
    int cb = (lane >> 3) & 1;
#pragma unroll
    for (int kk = 0; kk < 8; kk++) {
        uint32_t a[2][4], b[4][4];
#pragma unroll
        for (int mt = 0; mt < 2; mt++)
            ldm4(sa + swz(mo + mt * 16 + ra, kk * 2 + ca), a[mt]);
#pragma unroll
        for (int nt2 = 0; nt2 < 4; nt2++)
            ldm4(sb + swz(no + nt2 * 16 + rb, kk * 2 + cb), b[nt2]);
#pragma unroll
        for (int mt = 0; mt < 2; mt++)
#pragma unroll
            for (int nt = 0; nt < 8; nt++)
                mma16816(acc[mt][nt], a[mt],
                         b[nt >> 1][(nt & 1) * 2], b[nt >> 1][(nt & 1) * 2 + 1]);
    }
}

__device__ __forceinline__ void zacc(float acc[2][8][4]) {
#pragma unroll
    for (int mt = 0; mt < 2; mt++)
#pragma unroll
        for (int nt = 0; nt < 8; nt++)
#pragma unroll
            for (int j = 0; j < 4; j++) acc[mt][nt][j] = 0.0f;
}

// fp32 row-major 128x128 gmem -> bf16 swizzled smem tile (256 threads)
__device__ __forceinline__ void load_w(char* dst, const float* __restrict__ W, int tid) {
#pragma unroll
    for (int i = 0; i < 8; i++) {
        int idx = tid + i * 256;
        int row = idx >> 4, g = idx & 15;
        const float4* p = (const float4*)(W + row * 128 + g * 8);
        float4 v0 = p[0], v1 = p[1];
        uint4 o;
        o.x = pack_bf16(v0.x, v0.y);  o.y = pack_bf16(v0.z, v0.w);
        o.z = pack_bf16(v1.x, v1.y);  o.w = pack_bf16(v1.z, v1.w);
        *(uint4*)(dst + swz(row, g)) = o;
    }
}

// bf16 row-major 128x128 gmem -> swizzled smem tile
__device__ __forceinline__ void load_t(char* dst, const __nv_bfloat16* __restrict__ src, int tid) {
#pragma unroll
    for (int i = 0; i < 8; i++) {
        int idx = tid + i * 256;
        int row = idx >> 4, g = idx & 15;
        *(uint4*)(dst + swz(row, g)) = ((const uint4*)src)[idx];
    }
}

// accum -> bf16 row-major gmem tile
__device__ __forceinline__ void store_bf16(float acc[2][8][4],
                                           __nv_bfloat16* __restrict__ dst,
                                           int lane, int mo, int no) {
    int g = lane >> 2, t = lane & 3;
#pragma unroll
    for (int mt = 0; mt < 2; mt++)
#pragma unroll
        for (int nt = 0; nt < 8; nt++) {
            int col = no + nt * 8 + 2 * t;
            int r0 = mo + mt * 16 + g;
            *(uint32_t*)(dst + r0 * 128 + col)       = pack_bf16(acc[mt][nt][0], acc[mt][nt][1]);
            *(uint32_t*)(dst + (r0 + 8) * 128 + col) = pack_bf16(acc[mt][nt][2], acc[mt][nt][3]);
        }
}

// accum (optionally scaled) -> bf16 swizzled smem tile
__device__ __forceinline__ void store_sw(float acc[2][8][4], char* buf, float scale,
                                         int lane, int mo, int no) {
    int g = lane >> 2, t = lane & 3;
#pragma unroll
    for (int mt = 0; mt < 2; mt++)
#pragma unroll
        for (int nt = 0; nt < 8; nt++) {
            int col = no + nt * 8 + 2 * t;
            int r0 = mo + mt * 16 + g, r1 = r0 + 8;
            *(uint32_t*)(buf + swz(r0, col >> 3) + (col & 7) * 2) =
                pack_bf16(acc[mt][nt][0] * scale, acc[mt][nt][1] * scale);
            *(uint32_t*)(buf + swz(r1, col >> 3) + (col & 7) * 2) =
                pack_bf16(acc[mt][nt][2] * scale, acc[mt][nt][3] * scale);
        }
}

// ===========================================================================
// Kernel 1: LN1 + {Q, K, Kt, Vt} + fused per-chunk state St = Vt @ Kt^T.
// smem: b0=Tn@0, b1=W@32K, b2=Kt@64K  (96 KB -> 2 CTAs/SM)
// ===========================================================================
#define K1_SMEM (3 * 32768)

extern "C" __global__ void __launch_bounds__(256, 2)
k_ln1_qkv(const float* __restrict__ tokens,
          const float* __restrict__ Wq, const float* __restrict__ Wk,
          const float* __restrict__ Wv,
          const float* __restrict__ g1, const float* __restrict__ b1v) {
    extern __shared__ char smem[];
    char* b0 = smem;
    char* b1 = smem + 32768;
    char* b2 = smem + 65536;
    int tid = threadIdx.x, wid = tid >> 5, lane = tid & 31;
    int mo = (wid & 3) * 32, no = (wid >> 2) * 64;
    int cid = blockIdx.x, base = cid * CH;
    uint32_t sb0 = smem_u32(b0), sb1 = smem_u32(b1), sb2 = smem_u32(b2);

    // LN1 -> swizzled bf16 tile in b0
    for (int r = wid; r < CH; r += 8) {
        float4 v = ((const float4*)(tokens + (size_t)(base + r) * 128))[lane];
        float s  = v.x + v.y + v.z + v.w;
        float s2 = v.x * v.x + v.y * v.y + v.z * v.z + v.w * v.w;
#pragma unroll
        for (int o = 16; o; o >>= 1) {
            s  += __shfl_xor_sync(0xffffffffu, s, o);
            s2 += __shfl_xor_sync(0xffffffffu, s2, o);
        }
        float mu  = s * (1.0f / 128.0f);
        float var = fmaxf(s2 * (1.0f / 128.0f) - mu * mu, 0.0f);
        float inv = rsqrtf(var + 1e-5f);
        float4 gg = ((const float4*)g1)[lane];
        float4 bb = ((const float4*)b1v)[lane];
        float o0 = (v.x - mu) * inv * gg.x + bb.x;
        float o1 = (v.y - mu) * inv * gg.y + bb.y;
        float o2 = (v.z - mu) * inv * gg.z + bb.z;
        float o3 = (v.w - mu) * inv * gg.w + bb.w;
        uint32_t off = swz(r, lane >> 1) + (lane & 1) * 8;
        *(uint32_t*)(b0 + off)     = pack_bf16(o0, o1);
        *(uint32_t*)(b0 + off + 4) = pack_bf16(o2, o3);
    }
    load_w(b1, Wq, tid);
    __syncthreads();

    float acc[2][8][4];

    // Q = Tn @ Wq^T
    zacc(acc); mm_ss(sb0, sb1, acc, lane, mo, no);
    store_bf16(acc, g_Q + (size_t)cid * TILE, lane, mo, no);
    __syncthreads();                                 // b1 free
    load_w(b1, Wk, tid);
    __syncthreads();

    // K = Tn @ Wk^T ; Kt = Wk @ Tn^T  (Wk still resident)
    zacc(acc); mm_ss(sb0, sb1, acc, lane, mo, no);
    store_bf16(acc, g_K + (size_t)cid * TILE, lane, mo, no);
    zacc(acc); mm_ss(sb1, sb0, acc, lane, mo, no);
    store_sw(acc, b2, 1.0f, lane, mo, no);           // Kt -> b2
    __syncthreads();                                 // b1 free, b2 visible
    load_w(b1, Wv, tid);
    __syncthreads();

    // Vt = Wv @ Tn^T
    zacc(acc); mm_ss(sb1, sb0, acc, lane, mo, no);
    store_bf16(acc, g_Vt + (size_t)cid * TILE, lane, mo, no);
    __syncthreads();                                 // everyone done reading b0=Tn
    store_sw(acc, b0, 1.0f, lane, mo, no);           // Vt -> b0
    __syncthreads();

    // St = Vt @ Kt^T  -> fp32 g_S
    zacc(acc); mm_ss(sb0, sb2, acc, lane, mo, no);
    float* dst = g_S + (size_t)cid * TILE;
    int g = lane >> 2, t = lane & 3;
#pragma unroll
    for (int mt = 0; mt < 2; mt++)
#pragma unroll
        for (int nt = 0; nt < 8; nt++) {
            int col = no + nt * 8 + 2 * t;
            int r0 = mo + mt * 16 + g;
            *(float2*)(dst + r0 * 128 + col)       = make_float2(acc[mt][nt][0], acc[mt][nt][1]);
            *(float2*)(dst + (r0 + 8) * 128 + col) = make_float2(acc[mt][nt][2], acc[mt][nt][3]);
        }
}

// ===========================================================================
// Kernel 3: per-element exclusive prefix over chunks -> bf16 g_Mt
// ===========================================================================
extern "C" __global__ void __launch_bounds__(256)
k_prefix() {
    int t = blockIdx.x * 256 + threadIdx.x;   // 65536 threads
    int b = t >> 14, e = t & 16383;
    const float* S = g_S + (size_t)b * NCB * TILE + e;
    __nv_bfloat16* M = g_Mt + (size_t)b * NCB * TILE + e;
    float s = 0.0f;
#pragma unroll 4
    for (int c = 0; c < NCB; c++) {
        M[(size_t)c * TILE] = __float2bfloat16(s);
        s += S[(size_t)c * TILE];
    }
}

// ===========================================================================
// Kernel 4: scores = tril(Q K^T); attn = Q@Mt^T + P@Vt^T;
//           out = LN2(x + 0.1 * attn @ Wo^T)
// smem: b0@0, b1@32K, b2@64K (96 KB).  res fp32 (pitch 128) aliases b0+b1.
// Buffer life: b0: Q -> Vt;  b1: K -> P -> attn;  b2: Mt -> Wo.
// ===========================================================================
#define K4_SMEM (3 * 32768)

extern "C" __global__ void __launch_bounds__(256, 2)
k_attn_out(const float* __restrict__ tokens,
           const float* __restrict__ Wo,
           const float* __restrict__ g2, const float* __restrict__ b2v,
           float* __restrict__ out) {
    extern __shared__ char smem[];
    char* b0 = smem;
    char* b1 = smem + 32768;
    char* b2 = smem + 65536;
    float* res = (float*)smem;                     // 128 x 128 fp32 = 64KB (b0+b1)
    int tid = threadIdx.x, wid = tid >> 5, lane = tid & 31;
    int mo = (wid & 3) * 32, no = (wid >> 2) * 64;
    int g = lane >> 2, t = lane & 3;
    int cid = blockIdx.x, base = cid * CH;
    uint32_t sb0 = smem_u32(b0), sb1 = smem_u32(b1), sb2 = smem_u32(b2);

    load_t(b0, g_Q  + (size_t)cid * TILE, tid);
    load_t(b1, g_K  + (size_t)cid * TILE, tid);
    load_t(b2, g_Mt + (size_t)cid * TILE, tid);
    __syncthreads();

    float acc[2][8][4];

    // scores = Q @ K^T
    zacc(acc); mm_ss(sb0, sb1, acc, lane, mo, no);
    __syncthreads();                               // all warps done reading b1=K

    // masked P -> b1 (bf16 swizzled)
#pragma unroll
    for (int mt = 0; mt < 2; mt++)
#pragma unroll
        for (int nt = 0; nt < 8; nt++) {
            int col = no + nt * 8 + 2 * t;
            int r0 = mo + mt * 16 + g, r1 = r0 + 8;
            float v0 = (col     <= r0) ? acc[mt][nt][0] : 0.0f;
            float v1 = (col + 1 <= r0) ? acc[mt][nt][1] : 0.0f;
            float v2 = (col     <= r1) ? acc[mt][nt][2] : 0.0f;
            float v3 = (col + 1 <= r1) ? acc[mt][nt][3] : 0.0f;
            *(uint32_t*)(b1 + swz(r0, col >> 3) + (col & 7) * 2) = pack_bf16(v0, v1);
            *(uint32_t*)(b1 + swz(r1, col >> 3) + (col & 7) * 2) = pack_bf16(v2, v3);
        }
    __syncthreads();                               // P visible

    // attn = Q @ Mt^T   (part 1 of K=256 concat)
    zacc(acc); mm_ss(sb0, sb2, acc, lane, mo, no);
    __syncthreads();                               // b0=Q, b2=Mt dead
    load_t(b0, g_Vt + (size_t)cid * TILE, tid);
    load_w(b2, Wo, tid);
    __syncthreads();

    // attn += P @ Vt^T  (part 2, same accumulator)
    mm_ss(sb1, sb0, acc, lane, mo, no);
    __syncthreads();                               // all warps done reading b1=P

    // scaled attn -> b1 (bf16 swizzled)
    store_sw(acc, b1, RSQRT_H, lane, mo, no);
    __syncthreads();

    // proj = attn @ Wo^T
    zacc(acc); mm_ss(sb1, sb2, acc, lane, mo, no);
    __syncthreads();                               // b0/b1 free -> res region

    // 0.1*proj fragments -> res (pitch 128 fp32)
#pragma unroll
    for (int mt = 0; mt < 2; mt++)
#pragma unroll
        for (int nt = 0; nt < 8; nt++) {
            int col = no + nt * 8 + 2 * t;
            int r0 = mo + mt * 16 + g, r1 = r0 + 8;
            *(float2*)&res[r0 * 128 + col] = make_float2(0.1f * acc[mt][nt][0], 0.1f * acc[mt][nt][1]);
            *(float2*)&res[r1 * 128 + col] = make_float2(0.1f * acc[mt][nt][2], 0.1f * acc[mt][nt][3]);
        }
    __syncthreads();

    // fused: x = tokens + res ; LN2(x) -> out   (one coalesced pass, warp/row)
    for (int r = wid; r < CH; r += 8) {
        float4 tv = ((const float4*)(tokens + (size_t)(base + r) * 128))[lane];
        float4 pv = *(const float4*)&res[r * 128 + lane * 4];
        float x0 = tv.x + pv.x, x1 = tv.y + pv.y, x2 = tv.z + pv.z, x3 = tv.w + pv.w;
        float s  = x0 + x1 + x2 + x3;
        float s2 = x0 * x0 + x1 * x1 + x2 * x2 + x3 * x3;
#pragma unroll
        for (int o = 16; o; o >>= 1) {
            s  += __shfl_xor_sync(0xffffffffu, s, o);
            s2 += __shfl_xor_sync(0xffffffffu, s2, o);
        }
        float mu  = s * (1.0f / 128.0f);
        float var = fmaxf(s2 * (1.0f / 128.0f) - mu * mu, 0.0f);
        float inv = rsqrtf(var + 1e-5f);
        float4 gg = ((const float4*)g2)[lane];
        float4 bb = ((const float4*)b2v)[lane];
        float4 o4;
        o4.x = (x0 - mu) * inv * gg.x + bb.x;
        o4.y = (x1 - mu) * inv * gg.y + bb.y;
        o4.z = (x2 - mu) * inv * gg.z + bb.z;
        o4.w = (x3 - mu) * inv * gg.w + bb.w;
        ((float4*)(out + (size_t)(base + r) * 128))[lane] = o4;
    }
}

// ===========================================================================
extern "C" void kernel_launch(void* const* d_in, const int* in_sizes, int n_in,
                              void* d_out, int out_size) {
    const float* tokens = (const float*)d_in[0];
    const float* Wq = (const float*)d_in[1];
    const float* Wk = (const float*)d_in[2];
    const float* Wv = (const float*)d_in[3];
    const float* Wo = (const float*)d_in[4];
    const float* g1 = (const float*)d_in[5];
    const float* b1 = (const float*)d_in[6];
    const float* g2 = (const float*)d_in[7];
    const float* b2 = (const float*)d_in[8];
    float* out = (float*)d_out;

    cudaFuncSetAttribute(k_ln1_qkv,  cudaFuncAttributeMaxDynamicSharedMemorySize, K1_SMEM);
    cudaFuncSetAttribute(k_attn_out, cudaFuncAttributeMaxDynamicSharedMemorySize, K4_SMEM);

    k_ln1_qkv<<<NCHUNK, 256, K1_SMEM>>>(tokens, Wq, Wk, Wv, g1, b1);
    k_prefix<<<NCHUNK, 256>>>();
    k_attn_out<<<NCHUNK, 256, K4_SMEM>>>(tokens, Wo, g2, b2, out);
}

// round 5
// speedup vs baseline: 3.6637x; 1.0752x over previous
#include <cuda_runtime.h>
#include <cuda_bf16.h>
#include <stdint.h>

// ---------------------------------------------------------------------------
// Linear attention (causal QK^T, NO softmax) via chunked prefix-state.
// mma.sync.m16n8k16 bf16; ldmatrix.trans gives free transposes.
//   K0: weights fp32 -> bf16 (one-shot)
//   K1: LN1 + Q,K,V projections + fused state M_c[h][v] = K^T V (trans-MMA)
//   K2: exclusive prefix scan of states -> g_M (bf16)
//   K3: scores=tril(QK^T); attn = Q@M^T(+) P@V; out = LN2(x + 0.1*attn@Wo^T)
// ---------------------------------------------------------------------------

#define NB      4
#define NSEQ    8192
#define CH      128
#define NCB     (NSEQ / CH)        // 64
#define NCHUNK  (NB * NCB)         // 256
#define TILE    16384              // 128*128
#define RSQRT_H 0.08838834764831845f

// Scratch (device globals: allocation-free rule)
__device__ __nv_bfloat16 g_Q [NCHUNK * TILE];
__device__ __nv_bfloat16 g_K [NCHUNK * TILE];
__device__ __nv_bfloat16 g_V [NCHUNK * TILE];
__device__ float         g_S [NCHUNK * TILE];   // per-chunk state [h][v] fp32
__device__ __nv_bfloat16 g_M [NCHUNK * TILE];   // exclusive prefix state [h][v]
__device__ __nv_bfloat16 g_Wb[4 * TILE];        // bf16 weights: Wq,Wk,Wv,Wo

// =========================== helpers =======================================
__device__ __forceinline__ uint32_t smem_u32(const void* p) {
    uint32_t a;
    asm("{ .reg .u64 t; cvta.to.shared.u64 t, %1; cvt.u32.u64 %0, t; }"
        : "=r"(a) : "l"(p));
    return a;
}

// Swizzled byte offset inside a 128x128 bf16 tile (256B rows); colg = 16B group
__device__ __forceinline__ uint32_t swz(int row, int colg) {
    return (uint32_t)(row * 256) + (uint32_t)(((colg ^ (row & 7)) << 4));
}

__device__ __forceinline__ uint32_t pack_bf16(float lo, float hi) {
    __nv_bfloat162 h;
    h.x = __float2bfloat16(lo);
    h.y = __float2bfloat16(hi);
    return *reinterpret_cast<uint32_t*>(&h);
}

__device__ __forceinline__ void ldm4(uint32_t addr, uint32_t r[4]) {
    asm volatile("ldmatrix.sync.aligned.m8n8.x4.shared.b16 {%0,%1,%2,%3}, [%4];"
                 : "=r"(r[0]), "=r"(r[1]), "=r"(r[2]), "=r"(r[3]) : "r"(addr));
}
__device__ __forceinline__ void ldm4t(uint32_t addr, uint32_t r[4]) {
    asm volatile("ldmatrix.sync.aligned.m8n8.x4.trans.shared.b16 {%0,%1,%2,%3}, [%4];"
                 : "=r"(r[0]), "=r"(r[1]), "=r"(r[2]), "=r"(r[3]) : "r"(addr));
}

__device__ __forceinline__ void mma16816(float* c, const uint32_t a[4],
                                         uint32_t b0, uint32_t b1) {
    asm volatile(
        "mma.sync.aligned.m16n8k16.row.col.f32.bf16.bf16.f32 "
        "{%0,%1,%2,%3},{%4,%5,%6,%7},{%8,%9},{%0,%1,%2,%3};"
        : "+f"(c[0]), "+f"(c[1]), "+f"(c[2]), "+f"(c[3])
        : "r"(a[0]), "r"(a[1]), "r"(a[2]), "r"(a[3]), "r"(b0), "r"(b1));
}

// cp.async 128x128 bf16 gmem tile -> swizzled smem tile
__device__ __forceinline__ void cp_tile(uint32_t dst, const __nv_bfloat16* __restrict__ src,
                                        int tid) {
#pragma unroll
    for (int i = 0; i < 8; i++) {
        int idx = tid + i * 256;
        int row = idx >> 4, g = idx & 15;
        asm volatile("cp.async.cg.shared.global [%0], [%1], 16;"
                     :: "r"(dst + swz(row, g)),
                        "l"((const void*)(((const uint4*)src) + idx)));
    }
}
#define CP_COMMIT() asm volatile("cp.async.commit_group;" ::: "memory")
#define CP_WAIT()   asm volatile("cp.async.wait_all;" ::: "memory")

// ---------------------------------------------------------------------------
// 128x128x128: C[m][n] += A' * B'^T on swizzled bf16 smem tiles.
// ATR: A' = (tile at sa)^T, i.e. tile stored [k][m];  BTR: B' = (tile sb)^T.
// 8 warps: warp w owns rows mo=(w&3)*32, cols no=(w>>2)*64. acc[2][8][4].
// ---------------------------------------------------------------------------
template <int ATR, int BTR>
__device__ __forceinline__ void mm(uint32_t sa, uint32_t sb,
                                   float acc[2][8][4], int lane, int mo, int no) {
#pragma unroll
    for (int kk = 0; kk < 8; kk++) {
        uint32_t a[2][4], b[4][4];
#pragma unroll
        for (int mt = 0; mt < 2; mt++) {
            if (!ATR) {
                ldm4(sa + swz(mo + mt * 16 + (lane & 15), kk * 2 + (lane >> 4)), a[mt]);
            } else {
                ldm4t(sa + swz(kk * 16 + ((lane >> 4) << 3) + (lane & 7),
                               ((mo + mt * 16) >> 3) + ((lane >> 3) & 1)), a[mt]);
            }
        }
#pragma unroll
        for (int nt2 = 0; nt2 < 4; nt2++) {
            if (!BTR) {
                ldm4(sb + swz(no + nt2 * 16 + ((lane >> 4) << 3) + (lane & 7),
                              kk * 2 + ((lane >> 3) & 1)), b[nt2]);
            } else {
                ldm4t(sb + swz(kk * 16 + ((lane >> 3) & 1) * 8 + (lane & 7),
                               ((no + nt2 * 16) >> 3) + (lane >> 4)), b[nt2]);
            }
        }
#pragma unroll
        for (int mt = 0; mt < 2; mt++)
#pragma unroll
            for (int nt = 0; nt < 8; nt++)
                mma16816(acc[mt][nt], a[mt],
                         b[nt >> 1][(nt & 1) * 2], b[nt >> 1][(nt & 1) * 2 + 1]);
    }
}

__device__ __forceinline__ void zacc(float acc[2][8][4]) {
#pragma unroll
    for (int mt = 0; mt < 2; mt++)
#pragma unroll
        for (int nt = 0; nt < 8; nt++)
#pragma unroll
            for (int j = 0; j < 4; j++) acc[mt][nt][j] = 0.0f;
}

// accum -> bf16 row-major gmem tile
__device__ __forceinline__ void store_bf16(float acc[2][8][4],
                                           __nv_bfloat16* __restrict__ dst,
                                           int lane, int mo, int no) {
    int g = lane >> 2, t = lane & 3;
#pragma unroll
    for (int mt = 0; mt < 2; mt++)
#pragma unroll
        for (int nt = 0; nt < 8; nt++) {
            int col = no + nt * 8 + 2 * t;
            int r0 = mo + mt * 16 + g;
            *(uint32_t*)(dst + r0 * 128 + col)       = pack_bf16(acc[mt][nt][0], acc[mt][nt][1]);
            *(uint32_t*)(dst + (r0 + 8) * 128 + col) = pack_bf16(acc[mt][nt][2], acc[mt][nt][3]);
        }
}

// accum (scaled) -> bf16 swizzled smem tile
__device__ __forceinline__ void store_sw(float acc[2][8][4], char* buf, float scale,
                                         int lane, int mo, int no) {
    int g = lane >> 2, t = lane & 3;
#pragma unroll
    for (int mt = 0; mt < 2; mt++)
#pragma unroll
        for (int nt = 0; nt < 8; nt++) {
            int col = no + nt * 8 + 2 * t;
            int r0 = mo + mt * 16 + g, r1 = r0 + 8;
            *(uint32_t*)(buf + swz(r0, col >> 3) + (col & 7) * 2) =
                pack_bf16(acc[mt][nt][0] * scale, acc[mt][nt][1] * scale);
            *(uint32_t*)(buf + swz(r1, col >> 3) + (col & 7) * 2) =
                pack_bf16(acc[mt][nt][2] * scale, acc[mt][nt][3] * scale);
        }
}

// ===========================================================================
// Kernel 0: weights fp32 -> bf16 row-major gmem (one-shot, tiny)
// ===========================================================================
extern "C" __global__ void __launch_bounds__(256)
k_prep(const float* __restrict__ Wq, const float* __restrict__ Wk,
       const float* __restrict__ Wv, const float* __restrict__ Wo) {
    const float* srcs[4] = {Wq, Wk, Wv, Wo};
    int w = blockIdx.x >> 3, part = blockIdx.x & 7;
    const float4* s = (const float4*)(srcs[w] + part * 2048);
    uint32_t* d = (uint32_t*)(g_Wb + (size_t)w * TILE + part * 2048);
    int tid = threadIdx.x;
#pragma unroll
    for (int i = 0; i < 2; i++) {
        int idx = tid + i * 256;
        float4 v = s[idx];
        d[idx * 2]     = pack_bf16(v.x, v.y);
        d[idx * 2 + 1] = pack_bf16(v.z, v.w);
    }
}

// ===========================================================================
// Kernel 1: LN1 + {Q, K, V} + fused state M_c[h][v] = sum_j K[j][h] V[j][v]
// smem: b0 = Tn -> V ; b1 = Wq -> Wv ; b2 = Wk -> K   (96 KB, 2 CTAs/SM)
// ===========================================================================
#define K1_SMEM (3 * 32768)

extern "C" __global__ void __launch_bounds__(256, 2)
k_ln1_qkv(const float* __restrict__ tokens,
          const float* __restrict__ g1, const float* __restrict__ b1v) {
    extern __shared__ char smem[];
    char* b0 = smem;
    char* b1 = smem + 32768;
    char* b2 = smem + 65536;
    int tid = threadIdx.x, wid = tid >> 5, lane = tid & 31;
    int mo = (wid & 3) * 32, no = (wid >> 2) * 64;
    int cid = blockIdx.x, base = cid * CH;
    uint32_t sb0 = smem_u32(b0), sb1 = smem_u32(b1), sb2 = smem_u32(b2);

    // phase 0: prefetch Wq, Wk; LN1 -> b0 overlapped
    cp_tile(sb1, g_Wb, tid);
    cp_tile(sb2, g_Wb + TILE, tid);
    CP_COMMIT();

    for (int r = wid; r < CH; r += 8) {
        float4 v = ((const float4*)(tokens + (size_t)(base + r) * 128))[lane];
        float s  = v.x + v.y + v.z + v.w;
        float s2 = v.x * v.x + v.y * v.y + v.z * v.z + v.w * v.w;
#pragma unroll
        for (int o = 16; o; o >>= 1) {
            s  += __shfl_xor_sync(0xffffffffu, s, o);
            s2 += __shfl_xor_sync(0xffffffffu, s2, o);
        }
        float mu  = s * (1.0f / 128.0f);
        float var = fmaxf(s2 * (1.0f / 128.0f) - mu * mu, 0.0f);
        float inv = rsqrtf(var + 1e-5f);
        float4 gg = ((const float4*)g1)[lane];
        float4 bb = ((const float4*)b1v)[lane];
        float o0 = (v.x - mu) * inv * gg.x + bb.x;
        float o1 = (v.y - mu) * inv * gg.y + bb.y;
        float o2 = (v.z - mu) * inv * gg.z + bb.z;
        float o3 = (v.w - mu) * inv * gg.w + bb.w;
        uint32_t off = swz(r, lane >> 1) + (lane & 1) * 8;
        *(uint32_t*)(b0 + off)     = pack_bf16(o0, o1);
        *(uint32_t*)(b0 + off + 4) = pack_bf16(o2, o3);
    }
    CP_WAIT();
    __syncthreads();

    float acc[2][8][4];

    // phase 1: Q = Tn @ Wq^T
    zacc(acc);
    mm<0, 0>(sb0, sb1, acc, lane, mo, no);
    store_bf16(acc, g_Q + (size_t)cid * TILE, lane, mo, no);
    __syncthreads();                               // b1 free

    // phase 2: prefetch Wv -> b1 ; K = Tn @ Wk^T
    cp_tile(sb1, g_Wb + 2 * TILE, tid);
    CP_COMMIT();
    zacc(acc);
    mm<0, 0>(sb0, sb2, acc, lane, mo, no);
    store_bf16(acc, g_K + (size_t)cid * TILE, lane, mo, no);
    CP_WAIT();
    __syncthreads();                               // b2 (Wk) reads done

    // phase 3: K frags -> b2 ; V = Tn @ Wv^T
    store_sw(acc, b2, 1.0f, lane, mo, no);
    zacc(acc);
    mm<0, 0>(sb0, sb1, acc, lane, mo, no);
    store_bf16(acc, g_V + (size_t)cid * TILE, lane, mo, no);
    __syncthreads();                               // b0 (Tn) reads done

    // phase 4: V frags -> b0
    store_sw(acc, b0, 1.0f, lane, mo, no);
    __syncthreads();

    // phase 5: M_c = K^T @ V  via trans-loads: A = b2(K[j][h])^T, B = b0(V[j][v])^T
    zacc(acc);
    mm<1, 1>(sb2, sb0, acc, lane, mo, no);
    float* dst = g_S + (size_t)cid * TILE;
    int g = lane >> 2, t = lane & 3;
#pragma unroll
    for (int mt = 0; mt < 2; mt++)
#pragma unroll
        for (int nt = 0; nt < 8; nt++) {
            int col = no + nt * 8 + 2 * t;
            int r0 = mo + mt * 16 + g;
            *(float2*)(dst + r0 * 128 + col)       = make_float2(acc[mt][nt][0], acc[mt][nt][1]);
            *(float2*)(dst + (r0 + 8) * 128 + col) = make_float2(acc[mt][nt][2], acc[mt][nt][3]);
        }
}

// ===========================================================================
// Kernel 2: per-element exclusive prefix over chunks -> bf16 g_M
// ===========================================================================
extern "C" __global__ void __launch_bounds__(256)
k_prefix() {
    int t = blockIdx.x * 256 + threadIdx.x;   // 65536 threads
    int b = t >> 14, e = t & 16383;
    const float* S = g_S + (size_t)b * NCB * TILE + e;
    __nv_bfloat16* M = g_M + (size_t)b * NCB * TILE + e;
    float s = 0.0f;
#pragma unroll 4
    for (int c = 0; c < NCB; c++) {
        M[(size_t)c * TILE] = __float2bfloat16(s);
        s += S[(size_t)c * TILE];
    }
}

// ===========================================================================
// Kernel 3: scores = tril(Q K^T); attn = P@V + Q@M; out = LN2(x + 0.1*attn@Wo^T)
// smem: b0 = Q -> attn ; b1 = K -> P -> Wo ; b2 = V -> M -> res(bf16)
// ===========================================================================
#define K4_SMEM (3 * 32768)

extern "C" __global__ void __launch_bounds__(256, 2)
k_attn_out(const float* __restrict__ tokens,
           const float* __restrict__ g2, const float* __restrict__ b2v,
           float* __restrict__ out) {
    extern __shared__ char smem[];
    char* b0 = smem;
    char* b1 = smem + 32768;
    char* b2 = smem + 65536;
    int tid = threadIdx.x, wid = tid >> 5, lane = tid & 31;
    int mo = (wid & 3) * 32, no = (wid >> 2) * 64;
    int g = lane >> 2, t = lane & 3;
    int cid = blockIdx.x, base = cid * CH;
    uint32_t sb0 = smem_u32(b0), sb1 = smem_u32(b1), sb2 = smem_u32(b2);

    // phase 0: batch-load Q, K, V
    cp_tile(sb0, g_Q + (size_t)cid * TILE, tid);
    cp_tile(sb1, g_K + (size_t)cid * TILE, tid);
    cp_tile(sb2, g_V + (size_t)cid * TILE, tid);
    CP_COMMIT();
    CP_WAIT();
    __syncthreads();

    float acc[2][8][4];

    // phase 1: scores = Q @ K^T
    zacc(acc);
    mm<0, 0>(sb0, sb1, acc, lane, mo, no);
    __syncthreads();                               // K dead

    // phase 2: masked P -> b1
#pragma unroll
    for (int mt = 0; mt < 2; mt++)
#pragma unroll
        for (int nt = 0; nt < 8; nt++) {
            int col = no + nt * 8 + 2 * t;
            int r0 = mo + mt * 16 + g, r1 = r0 + 8;
            float v0 = (col     <= r0) ? acc[mt][nt][0] : 0.0f;
            float v1 = (col + 1 <= r0) ? acc[mt][nt][1] : 0.0f;
            float v2 = (col     <= r1) ? acc[mt][nt][2] : 0.0f;
            float v3 = (col + 1 <= r1) ? acc[mt][nt][3] : 0.0f;
            *(uint32_t*)(b1 + swz(r0, col >> 3) + (col & 7) * 2) = pack_bf16(v0, v1);
            *(uint32_t*)(b1 + swz(r1, col >> 3) + (col & 7) * 2) = pack_bf16(v2, v3);
        }
    __syncthreads();                               // P visible

    // phase 3: attn = P @ V   (B = V[j][v] trans-loaded)
    zacc(acc);
    mm<0, 1>(sb1, sb2, acc, lane, mo, no);
    __syncthreads();                               // V, P dead

    // phase 4: load M -> b2, Wo -> b1
    cp_tile(sb2, g_M + (size_t)cid * TILE, tid);
    cp_tile(sb1, g_Wb + 3 * TILE, tid);
    CP_COMMIT();
    CP_WAIT();
    __syncthreads();

    // phase 5: attn += Q @ M  (B = M[h][v] trans-loaded)
    mm<0, 1>(sb0, sb2, acc, lane, mo, no);
    __syncthreads();                               // Q, M dead

    // phase 6: scaled attn -> b0
    store_sw(acc, b0, RSQRT_H, lane, mo, no);
    __syncthreads();

    // phase 7: proj = attn @ Wo^T ; 0.1*proj -> b2 as bf16 row-major
    zacc(acc);
    mm<0, 0>(sb0, sb1, acc, lane, mo, no);
#pragma unroll
    for (int mt = 0; mt < 2; mt++)
#pragma unroll
        for (int nt = 0; nt < 8; nt++) {
            int col = no + nt * 8 + 2 * t;
            int r0 = mo + mt * 16 + g, r1 = r0 + 8;
            *(uint32_t*)(b2 + (r0 * 128 + col) * 2) =
                pack_bf16(0.1f * acc[mt][nt][0], 0.1f * acc[mt][nt][1]);
            *(uint32_t*)(b2 + (r1 * 128 + col) * 2) =
                pack_bf16(0.1f * acc[mt][nt][2], 0.1f * acc[mt][nt][3]);
        }
    __syncthreads();

    // phase 8: LN2(tokens + res) -> out
    for (int r = wid; r < CH; r += 8) {
        float4 tv = ((const float4*)(tokens + (size_t)(base + r) * 128))[lane];
        uint2 pr = *(const uint2*)(b2 + (r * 128 + lane * 4) * 2);
        __nv_bfloat162 p0 = *reinterpret_cast<__nv_bfloat162*>(&pr.x);
        __nv_bfloat162 p1 = *reinterpret_cast<__nv_bfloat162*>(&pr.y);
        float x0 = tv.x + __bfloat162float(p0.x);
        float x1 = tv.y + __bfloat162float(p0.y);
        float x2 = tv.z + __bfloat162float(p1.x);
        float x3 = tv.w + __bfloat162float(p1.y);
        float s  = x0 + x1 + x2 + x3;
        float s2 = x0 * x0 + x1 * x1 + x2 * x2 + x3 * x3;
#pragma unroll
        for (int o = 16; o; o >>= 1) {
            s  += __shfl_xor_sync(0xffffffffu, s, o);
            s2 += __shfl_xor_sync(0xffffffffu, s2, o);
        }
        float mu  = s * (1.0f / 128.0f);
        float var = fmaxf(s2 * (1.0f / 128.0f) - mu * mu, 0.0f);
        float inv = rsqrtf(var + 1e-5f);
        float4 gg = ((const float4*)g2)[lane];
        float4 bb = ((const float4*)b2v)[lane];
        float4 o4;
        o4.x = (x0 - mu) * inv * gg.x + bb.x;
        o4.y = (x1 - mu) * inv * gg.y + bb.y;
        o4.z = (x2 - mu) * inv * gg.z + bb.z;
        o4.w = (x3 - mu) * inv * gg.w + bb.w;
        ((float4*)(out + (size_t)(base + r) * 128))[lane] = o4;
    }
}

// ===========================================================================
extern "C" void kernel_launch(void* const* d_in, const int* in_sizes, int n_in,
                              void* d_out, int out_size) {
    const float* tokens = (const float*)d_in[0];
    const float* Wq = (const float*)d_in[1];
    const float* Wk = (const float*)d_in[2];
    const float* Wv = (const float*)d_in[3];
    const float* Wo = (const float*)d_in[4];
    const float* g1 = (const float*)d_in[5];
    const float* b1 = (const float*)d_in[6];
    const float* g2 = (const float*)d_in[7];
    const float* b2 = (const float*)d_in[8];
    float* out = (float*)d_out;

    cudaFuncSetAttribute(k_ln1_qkv,  cudaFuncAttributeMaxDynamicSharedMemorySize, K1_SMEM);
    cudaFuncSetAttribute(k_attn_out, cudaFuncAttributeMaxDynamicSharedMemorySize, K4_SMEM);

    k_prep<<<32, 256>>>(Wq, Wk, Wv, Wo);
    k_ln1_qkv<<<NCHUNK, 256, K1_SMEM>>>(tokens, g1, b1);
    k_prefix<<<NCHUNK, 256>>>();
    k_attn_out<<<NCHUNK, 256, K4_SMEM>>>(tokens, g2, b2, out);
}

// round 6
// speedup vs baseline: 4.0899x; 1.1163x over previous
#include <cuda_runtime.h>
#include <cuda_bf16.h>
#include <stdint.h>

// ---------------------------------------------------------------------------
// Linear attention (causal QK^T, NO softmax) via chunked prefix-state.
// ONE persistent kernel (grid 256 = co-resident at 2 CTAs/SM) with software
// grid barriers:
//   phase A: LN1 + Q,K,V projections + chunk state S = K^T V   (K,V stay in smem)
//   phase B: grid-wide exclusive prefix scan S -> M  (Q prefetched under scan)
//   phase C: scores=tril(QK^T); attn = P@V + Q@M; out = LN2(x + 0.1*attn@Wo^T)
// ---------------------------------------------------------------------------

#define NB      4
#define NSEQ    8192
#define CH      128
#define NCB     (NSEQ / CH)        // 64
#define NCHUNK  (NB * NCB)         // 256
#define TILE    16384              // 128*128
#define RSQRT_H 0.08838834764831845f

// Scratch (device globals: allocation-free rule)
__device__ __nv_bfloat16 g_Q [NCHUNK * TILE];
__device__ __nv_bfloat16 g_S [NCHUNK * TILE];   // per-chunk state [h][v]
__device__ __nv_bfloat16 g_M [NCHUNK * TILE];   // exclusive prefix state [h][v]
__device__ __nv_bfloat16 g_Wb[4 * TILE];        // bf16 weights: Wq,Wk,Wv,Wo

// grid barrier state (zero-init; gen monotonically grows across graph replays)
__device__ int g_cnt = 0;
__device__ int g_gen = 0;

__device__ __forceinline__ void grid_bar() {
    __syncthreads();
    if (threadIdx.x == 0) {
        __threadfence();
        int gen = *((volatile int*)&g_gen);
        if (atomicAdd(&g_cnt, 1) == NCHUNK - 1) {
            g_cnt = 0;
            __threadfence();
            atomicExch(&g_gen, gen + 1);
        } else {
            while (*((volatile int*)&g_gen) == gen) __nanosleep(32);
        }
        __threadfence();
    }
    __syncthreads();
}

// =========================== helpers =======================================
__device__ __forceinline__ uint32_t smem_u32(const void* p) {
    uint32_t a;
    asm("{ .reg .u64 t; cvta.to.shared.u64 t, %1; cvt.u32.u64 %0, t; }"
        : "=r"(a) : "l"(p));
    return a;
}

// Swizzled byte offset inside a 128x128 bf16 tile (256B rows); colg = 16B group
__device__ __forceinline__ uint32_t swz(int row, int colg) {
    return (uint32_t)(row * 256) + (uint32_t)(((colg ^ (row & 7)) << 4));
}

__device__ __forceinline__ uint32_t pack_bf16(float lo, float hi) {
    __nv_bfloat162 h;
    h.x = __float2bfloat16(lo);
    h.y = __float2bfloat16(hi);
    return *reinterpret_cast<uint32_t*>(&h);
}

__device__ __forceinline__ void ldm4(uint32_t addr, uint32_t r[4]) {
    asm volatile("ldmatrix.sync.aligned.m8n8.x4.shared.b16 {%0,%1,%2,%3}, [%4];"
                 : "=r"(r[0]), "=r"(r[1]), "=r"(r[2]), "=r"(r[3]) : "r"(addr));
}
__device__ __forceinline__ void ldm4t(uint32_t addr, uint32_t r[4]) {
    asm volatile("ldmatrix.sync.aligned.m8n8.x4.trans.shared.b16 {%0,%1,%2,%3}, [%4];"
                 : "=r"(r[0]), "=r"(r[1]), "=r"(r[2]), "=r"(r[3]) : "r"(addr));
}

__device__ __forceinline__ void mma16816(float* c, const uint32_t a[4],
                                         uint32_t b0, uint32_t b1) {
    asm volatile(
        "mma.sync.aligned.m16n8k16.row.col.f32.bf16.bf16.f32 "
        "{%0,%1,%2,%3},{%4,%5,%6,%7},{%8,%9},{%0,%1,%2,%3};"
        : "+f"(c[0]), "+f"(c[1]), "+f"(c[2]), "+f"(c[3])
        : "r"(a[0]), "r"(a[1]), "r"(a[2]), "r"(a[3]), "r"(b0), "r"(b1));
}

// cp.async 128x128 bf16 gmem tile -> swizzled smem tile
__device__ __forceinline__ void cp_tile(uint32_t dst, const __nv_bfloat16* __restrict__ src,
                                        int tid) {
#pragma unroll
    for (int i = 0; i < 8; i++) {
        int idx = tid + i * 256;
        int row = idx >> 4, g = idx & 15;
        asm volatile("cp.async.cg.shared.global [%0], [%1], 16;"
                     :: "r"(dst + swz(row, g)),
                        "l"((const void*)(((const uint4*)src) + idx)));
    }
}
#define CP_COMMIT() asm volatile("cp.async.commit_group;" ::: "memory")
#define CP_WAIT()   asm volatile("cp.async.wait_all;" ::: "memory")

// ---------------------------------------------------------------------------
// 128x128x128: C[m][n] += A' * B'^T on swizzled bf16 smem tiles.
// ATR/BTR: operand is the smem tile transposed (ldmatrix.trans).
// 8 warps: warp w owns rows mo=(w&3)*32, cols no=(w>>2)*64. acc[2][8][4].
// ---------------------------------------------------------------------------
template <int ATR, int BTR>
__device__ __forceinline__ void mm(uint32_t sa, uint32_t sb,
                                   float acc[2][8][4], int lane, int mo, int no) {
#pragma unroll
    for (int kk = 0; kk < 8; kk++) {
        uint32_t a[2][4], b[4][4];
#pragma unroll
        for (int mt = 0; mt < 2; mt++) {
            if (!ATR) {
                ldm4(sa + swz(mo + mt * 16 + (lane & 15), kk * 2 + (lane >> 4)), a[mt]);
            } else {
                ldm4t(sa + swz(kk * 16 + ((lane >> 4) << 3) + (lane & 7),
                               ((mo + mt * 16) >> 3) + ((lane >> 3) & 1)), a[mt]);
            }
        }
#pragma unroll
        for (int nt2 = 0; nt2 < 4; nt2++) {
            if (!BTR) {
                ldm4(sb + swz(no + nt2 * 16 + ((lane >> 4) << 3) + (lane & 7),
                              kk * 2 + ((lane >> 3) & 1)), b[nt2]);
            } else {
                ldm4t(sb + swz(kk * 16 + ((lane >> 3) & 1) * 8 + (lane & 7),
                               ((no + nt2 * 16) >> 3) + (lane >> 4)), b[nt2]);
            }
        }
#pragma unroll
        for (int mt = 0; mt < 2; mt++)
#pragma unroll
            for (int nt = 0; nt < 8; nt++)
                mma16816(acc[mt][nt], a[mt],
                         b[nt >> 1][(nt & 1) * 2], b[nt >> 1][(nt & 1) * 2 + 1]);
    }
}

__device__ __forceinline__ void zacc(float acc[2][8][4]) {
#pragma unroll
    for (int mt = 0; mt < 2; mt++)
#pragma unroll
        for (int nt = 0; nt < 8; nt++)
#pragma unroll
            for (int j = 0; j < 4; j++) acc[mt][nt][j] = 0.0f;
}

// accum -> bf16 row-major gmem tile
__device__ __forceinline__ void store_bf16(float acc[2][8][4],
                                           __nv_bfloat16* __restrict__ dst,
                                           int lane, int mo, int no) {
    int g = lane >> 2, t = lane & 3;
#pragma unroll
    for (int mt = 0; mt < 2; mt++)
#pragma unroll
        for (int nt = 0; nt < 8; nt++) {
            int col = no + nt * 8 + 2 * t;
            int r0 = mo + mt * 16 + g;
            *(uint32_t*)(dst + r0 * 128 + col)       = pack_bf16(acc[mt][nt][0], acc[mt][nt][1]);
            *(uint32_t*)(dst + (r0 + 8) * 128 + col) = pack_bf16(acc[mt][nt][2], acc[mt][nt][3]);
        }
}

// accum (scaled) -> bf16 swizzled smem tile
__device__ __forceinline__ void store_sw(float acc[2][8][4], char* buf, float scale,
                                         int lane, int mo, int no) {
    int g = lane >> 2, t = lane & 3;
#pragma unroll
    for (int mt = 0; mt < 2; mt++)
#pragma unroll
        for (int nt = 0; nt < 8; nt++) {
            int col = no + nt * 8 + 2 * t;
            int r0 = mo + mt * 16 + g, r1 = r0 + 8;
            *(uint32_t*)(buf + swz(r0, col >> 3) + (col & 7) * 2) =
                pack_bf16(acc[mt][nt][0] * scale, acc[mt][nt][1] * scale);
            *(uint32_t*)(buf + swz(r1, col >> 3) + (col & 7) * 2) =
                pack_bf16(acc[mt][nt][2] * scale, acc[mt][nt][3] * scale);
        }
}

// ===========================================================================
// Kernel 0: weights fp32 -> bf16 row-major gmem (one-shot, tiny)
// ===========================================================================
extern "C" __global__ void __launch_bounds__(256)
k_prep(const float* __restrict__ Wq, const float* __restrict__ Wk,
       const float* __restrict__ Wv, const float* __restrict__ Wo) {
    const float* srcs[4] = {Wq, Wk, Wv, Wo};
    int w = blockIdx.x >> 3, part = blockIdx.x & 7;
    const float4* s = (const float4*)(srcs[w] + part * 2048);
    uint32_t* d = (uint32_t*)(g_Wb + (size_t)w * TILE + part * 2048);
    int tid = threadIdx.x;
#pragma unroll
    for (int i = 0; i < 2; i++) {
        int idx = tid + i * 256;
        float4 v = s[idx];
        d[idx * 2]     = pack_bf16(v.x, v.y);
        d[idx * 2 + 1] = pack_bf16(v.z, v.w);
    }
}

// ===========================================================================
// Fused persistent kernel. smem: b0 / b1 / b2 (3 x 32KB).
// Phase A buffers: b0 = Tn -> V ; b1 = Wq -> Wv -> (Q prefetch) ; b2 = Wk -> K
// Phase C buffers: b0 = V -> M -> res ; b1 = Q -> attn ; b2 = K -> P -> Wo
// ===========================================================================
#define KF_SMEM (3 * 32768)

extern "C" __global__ void __launch_bounds__(256, 2)
k_fused(const float* __restrict__ tokens,
        const float* __restrict__ g1, const float* __restrict__ b1v,
        const float* __restrict__ g2, const float* __restrict__ b2v,
        float* __restrict__ out) {
    extern __shared__ char smem[];
    char* b0 = smem;
    char* b1 = smem + 32768;
    char* b2 = smem + 65536;
    int tid = threadIdx.x, wid = tid >> 5, lane = tid & 31;
    int mo = (wid & 3) * 32, no = (wid >> 2) * 64;
    int g = lane >> 2, t = lane & 3;
    int cid = blockIdx.x, base = cid * CH;
    uint32_t sb0 = smem_u32(b0), sb1 = smem_u32(b1), sb2 = smem_u32(b2);

    float acc[2][8][4];

    // ============================ PHASE A ==================================
    // prefetch Wq, Wk while computing LN1 -> b0
    cp_tile(sb1, g_Wb, tid);
    cp_tile(sb2, g_Wb + TILE, tid);
    CP_COMMIT();

    for (int r = wid; r < CH; r += 8) {
        float4 v = ((const float4*)(tokens + (size_t)(base + r) * 128))[lane];
        float s  = v.x + v.y + v.z + v.w;
        float s2 = v.x * v.x + v.y * v.y + v.z * v.z + v.w * v.w;
#pragma unroll
        for (int o = 16; o; o >>= 1) {
            s  += __shfl_xor_sync(0xffffffffu, s, o);
            s2 += __shfl_xor_sync(0xffffffffu, s2, o);
        }
        float mu  = s * (1.0f / 128.0f);
        float var = fmaxf(s2 * (1.0f / 128.0f) - mu * mu, 0.0f);
        float inv = rsqrtf(var + 1e-5f);
        float4 gg = ((const float4*)g1)[lane];
        float4 bb = ((const float4*)b1v)[lane];
        float o0 = (v.x - mu) * inv * gg.x + bb.x;
        float o1 = (v.y - mu) * inv * gg.y + bb.y;
        float o2 = (v.z - mu) * inv * gg.z + bb.z;
        float o3 = (v.w - mu) * inv * gg.w + bb.w;
        uint32_t off = swz(r, lane >> 1) + (lane & 1) * 8;
        *(uint32_t*)(b0 + off)     = pack_bf16(o0, o1);
        *(uint32_t*)(b0 + off + 4) = pack_bf16(o2, o3);
    }
    CP_WAIT();
    __syncthreads();

    // Q = Tn @ Wq^T -> gmem (only Q round-trips)
    zacc(acc);
    mm<0, 0>(sb0, sb1, acc, lane, mo, no);
    store_bf16(acc, g_Q + (size_t)cid * TILE, lane, mo, no);
    __syncthreads();                               // b1 (Wq) dead

    // prefetch Wv -> b1 ; K = Tn @ Wk^T
    cp_tile(sb1, g_Wb + 2 * TILE, tid);
    CP_COMMIT();
    zacc(acc);
    mm<0, 0>(sb0, sb2, acc, lane, mo, no);
    CP_WAIT();
    __syncthreads();                               // b2 (Wk) dead everywhere

    // K frags -> b2 (resident through phase C!) ; V = Tn @ Wv^T
    store_sw(acc, b2, 1.0f, lane, mo, no);
    zacc(acc);
    mm<0, 0>(sb0, sb1, acc, lane, mo, no);
    __syncthreads();                               // b0 (Tn) dead, K visible

    // V frags -> b0 (resident through phase C!)
    store_sw(acc, b0, 1.0f, lane, mo, no);
    __syncthreads();

    // S = K^T @ V  (both trans-loaded) -> g_S bf16
    zacc(acc);
    mm<1, 1>(sb2, sb0, acc, lane, mo, no);
    store_bf16(acc, g_S + (size_t)cid * TILE, lane, mo, no);

    grid_bar();                                    // all S visible

    // ============================ PHASE B ==================================
    // prefetch own Q -> b1 under the scan
    cp_tile(sb1, g_Q + (size_t)cid * TILE, tid);
    CP_COMMIT();

    {
        int tg = cid * 256 + tid;                  // 65536 threads == elements
        int b = tg >> 14, e = tg & 16383;
        const __nv_bfloat16* S = g_S + (size_t)b * NCB * TILE + e;
        __nv_bfloat16* M = g_M + (size_t)b * NCB * TILE + e;
        float s = 0.0f;
#pragma unroll 8
        for (int c = 0; c < NCB; c++) {
            M[(size_t)c * TILE] = __float2bfloat16(s);
            s += __bfloat162float(S[(size_t)c * TILE]);
        }
    }

    grid_bar();                                    // all M visible
    CP_WAIT();
    __syncthreads();                               // Q in b1

    // ============================ PHASE C ==================================
    // scores = Q @ K^T   (Q=b1, K=b2 resident)
    zacc(acc);
    mm<0, 0>(sb1, sb2, acc, lane, mo, no);
    __syncthreads();                               // K dead

    // masked P -> b2
#pragma unroll
    for (int mt = 0; mt < 2; mt++)
#pragma unroll
        for (int nt = 0; nt < 8; nt++) {
            int col = no + nt * 8 + 2 * t;
            int r0 = mo + mt * 16 + g, r1 = r0 + 8;
            float v0 = (col     <= r0) ? acc[mt][nt][0] : 0.0f;
            float v1 = (col + 1 <= r0) ? acc[mt][nt][1] : 0.0f;
            float v2 = (col     <= r1) ? acc[mt][nt][2] : 0.0f;
            float v3 = (col + 1 <= r1) ? acc[mt][nt][3] : 0.0f;
            *(uint32_t*)(b2 + swz(r0, col >> 3) + (col & 7) * 2) = pack_bf16(v0, v1);
            *(uint32_t*)(b2 + swz(r1, col >> 3) + (col & 7) * 2) = pack_bf16(v2, v3);
        }
    __syncthreads();                               // P visible

    // attn = P @ V   (V=b0 resident, trans-loaded)
    zacc(acc);
    mm<0, 1>(sb2, sb0, acc, lane, mo, no);
    __syncthreads();                               // P, V dead

    // load M -> b0, Wo -> b2
    cp_tile(sb0, g_M + (size_t)cid * TILE, tid);
    cp_tile(sb2, g_Wb + 3 * TILE, tid);
    CP_COMMIT();
    CP_WAIT();
    __syncthreads();

    // attn += Q @ M  (M trans-loaded)
    mm<0, 1>(sb1, sb0, acc, lane, mo, no);
    __syncthreads();                               // Q, M dead

    // scaled attn -> b1
    store_sw(acc, b1, RSQRT_H, lane, mo, no);
    __syncthreads();

    // proj = attn @ Wo^T ; 0.1*proj -> b0 bf16 row-major
    zacc(acc);
    mm<0, 0>(sb1, sb2, acc, lane, mo, no);
#pragma unroll
    for (int mt = 0; mt < 2; mt++)
#pragma unroll
        for (int nt = 0; nt < 8; nt++) {
            int col = no + nt * 8 + 2 * t;
            int r0 = mo + mt * 16 + g, r1 = r0 + 8;
            *(uint32_t*)(b0 + (r0 * 128 + col) * 2) =
                pack_bf16(0.1f * acc[mt][nt][0], 0.1f * acc[mt][nt][1]);
            *(uint32_t*)(b0 + (r1 * 128 + col) * 2) =
                pack_bf16(0.1f * acc[mt][nt][2], 0.1f * acc[mt][nt][3]);
        }
    __syncthreads();

    // LN2(tokens + res) -> out
    for (int r = wid; r < CH; r += 8) {
        float4 tv = ((const float4*)(tokens + (size_t)(base + r) * 128))[lane];
        uint2 pr = *(const uint2*)(b0 + (r * 128 + lane * 4) * 2);
        __nv_bfloat162 p0 = *reinterpret_cast<__nv_bfloat162*>(&pr.x);
        __nv_bfloat162 p1 = *reinterpret_cast<__nv_bfloat162*>(&pr.y);
        float x0 = tv.x + __bfloat162float(p0.x);
        float x1 = tv.y + __bfloat162float(p0.y);
        float x2 = tv.z + __bfloat162float(p1.x);
        float x3 = tv.w + __bfloat162float(p1.y);
        float s  = x0 + x1 + x2 + x3;
        float s2 = x0 * x0 + x1 * x1 + x2 * x2 + x3 * x3;
#pragma unroll
        for (int o = 16; o; o >>= 1) {
            s  += __shfl_xor_sync(0xffffffffu, s, o);
            s2 += __shfl_xor_sync(0xffffffffu, s2, o);
        }
        float mu  = s * (1.0f / 128.0f);
        float var = fmaxf(s2 * (1.0f / 128.0f) - mu * mu, 0.0f);
        float inv = rsqrtf(var + 1e-5f);
        float4 gg = ((const float4*)g2)[lane];
        float4 bb = ((const float4*)b2v)[lane];
        float4 o4;
        o4.x = (x0 - mu) * inv * gg.x + bb.x;
        o4.y = (x1 - mu) * inv * gg.y + bb.y;
        o4.z = (x2 - mu) * inv * gg.z + bb.z;
        o4.w = (x3 - mu) * inv * gg.w + bb.w;
        ((float4*)(out + (size_t)(base + r) * 128))[lane] = o4;
    }
}

// ===========================================================================
extern "C" void kernel_launch(void* const* d_in, const int* in_sizes, int n_in,
                              void* d_out, int out_size) {
    const float* tokens = (const float*)d_in[0];
    const float* Wq = (const float*)d_in[1];
    const float* Wk = (const float*)d_in[2];
    const float* Wv = (const float*)d_in[3];
    const float* Wo = (const float*)d_in[4];
    const float* g1 = (const float*)d_in[5];
    const float* b1 = (const float*)d_in[6];
    const float* g2 = (const float*)d_in[7];
    const float* b2 = (const float*)d_in[8];
    float* out = (float*)d_out;

    cudaFuncSetAttribute(k_fused, cudaFuncAttributeMaxDynamicSharedMemorySize, KF_SMEM);

    k_prep<<<32, 256>>>(Wq, Wk, Wv, Wo);
    k_fused<<<NCHUNK, 256, KF_SMEM>>>(tokens, g1, b1, g2, b2, out);
}

// round 7
// speedup vs baseline: 4.1991x; 1.0267x over previous
#include <cuda_runtime.h>
#include <cuda_bf16.h>
#include <stdint.h>

// ---------------------------------------------------------------------------
// Linear attention (causal QK^T, NO softmax) via chunked prefix-state, with
// the projections folded into precomputed G = Wq^T Wk / sqrt(H), W2 = Wo Wv:
//   scores = Tn G Tn^T ; Z = tril(scores) @ Tn + (Tn G) @ Tpre ; proj = Z W2^T
// where T_c = Tn_c^T Tn_c and Tpre = exclusive prefix sum of T over chunks.
// ONE persistent kernel (grid 256 co-resident at 2 CTAs/SM) + grid barriers.
// Per-chunk MMAs: 6 (was 9). Only T/Tpre round-trip gmem.
// ---------------------------------------------------------------------------

#define NB      4
#define NSEQ    8192
#define CH      128
#define NCB     (NSEQ / CH)        // 64
#define NCHUNK  (NB * NCB)         // 256
#define TILE    16384              // 128*128
#define RSQRT_H 0.08838834764831845f

// Scratch (device globals: allocation-free rule)
__device__ __nv_bfloat16 g_S [NCHUNK * TILE];   // per-chunk gram T_c
__device__ __nv_bfloat16 g_M [NCHUNK * TILE];   // exclusive prefix Tpre
__device__ __nv_bfloat16 g_Wb[4 * TILE];        // bf16 weights: Wq,Wk,Wv,Wo
__device__ __nv_bfloat16 g_G [TILE];            // Wq^T Wk / sqrt(H)
__device__ __nv_bfloat16 g_W2[TILE];            // Wo @ Wv

// grid barrier state (zero-init; gen monotonically grows across graph replays)
__device__ int g_cnt = 0;
__device__ int g_gen = 0;

__device__ __forceinline__ void grid_bar() {
    __syncthreads();
    if (threadIdx.x == 0) {
        __threadfence();
        int gen = *((volatile int*)&g_gen);
        if (atomicAdd(&g_cnt, 1) == NCHUNK - 1) {
            g_cnt = 0;
            __threadfence();
            atomicExch(&g_gen, gen + 1);
        } else {
            while (*((volatile int*)&g_gen) == gen) __nanosleep(32);
        }
        __threadfence();
    }
    __syncthreads();
}

// =========================== helpers =======================================
__device__ __forceinline__ uint32_t smem_u32(const void* p) {
    uint32_t a;
    asm("{ .reg .u64 t; cvta.to.shared.u64 t, %1; cvt.u32.u64 %0, t; }"
        : "=r"(a) : "l"(p));
    return a;
}

// Swizzled byte offset inside a 128x128 bf16 tile (256B rows); colg = 16B group
__device__ __forceinline__ uint32_t swz(int row, int colg) {
    return (uint32_t)(row * 256) + (uint32_t)(((colg ^ (row & 7)) << 4));
}

__device__ __forceinline__ uint32_t pack_bf16(float lo, float hi) {
    __nv_bfloat162 h;
    h.x = __float2bfloat16(lo);
    h.y = __float2bfloat16(hi);
    return *reinterpret_cast<uint32_t*>(&h);
}

__device__ __forceinline__ void ldm4(uint32_t addr, uint32_t r[4]) {
    asm volatile("ldmatrix.sync.aligned.m8n8.x4.shared.b16 {%0,%1,%2,%3}, [%4];"
                 : "=r"(r[0]), "=r"(r[1]), "=r"(r[2]), "=r"(r[3]) : "r"(addr));
}
__device__ __forceinline__ void ldm4t(uint32_t addr, uint32_t r[4]) {
    asm volatile("ldmatrix.sync.aligned.m8n8.x4.trans.shared.b16 {%0,%1,%2,%3}, [%4];"
                 : "=r"(r[0]), "=r"(r[1]), "=r"(r[2]), "=r"(r[3]) : "r"(addr));
}

__device__ __forceinline__ void mma16816(float* c, const uint32_t a[4],
                                         uint32_t b0, uint32_t b1) {
    asm volatile(
        "mma.sync.aligned.m16n8k16.row.col.f32.bf16.bf16.f32 "
        "{%0,%1,%2,%3},{%4,%5,%6,%7},{%8,%9},{%0,%1,%2,%3};"
        : "+f"(c[0]), "+f"(c[1]), "+f"(c[2]), "+f"(c[3])
        : "r"(a[0]), "r"(a[1]), "r"(a[2]), "r"(a[3]), "r"(b0), "r"(b1));
}

// cp.async 128x128 bf16 gmem tile -> swizzled smem tile
__device__ __forceinline__ void cp_tile(uint32_t dst, const __nv_bfloat16* __restrict__ src,
                                        int tid) {
#pragma unroll
    for (int i = 0; i < 8; i++) {
        int idx = tid + i * 256;
        int row = idx >> 4, g = idx & 15;
        asm volatile("cp.async.cg.shared.global [%0], [%1], 16;"
                     :: "r"(dst + swz(row, g)),
                        "l"((const void*)(((const uint4*)src) + idx)));
    }
}
#define CP_COMMIT() asm volatile("cp.async.commit_group;" ::: "memory")
#define CP_WAIT()   asm volatile("cp.async.wait_all;" ::: "memory")

// ---------------------------------------------------------------------------
// 128x128x128: C[m][n] += A' * B'^T on swizzled bf16 smem tiles.
// ATR/BTR: operand is the smem tile transposed (ldmatrix.trans).
// 8 warps: warp w owns rows mo=(w&3)*32, cols no=(w>>2)*64. acc[2][8][4].
// ---------------------------------------------------------------------------
template <int ATR, int BTR>
__device__ __forceinline__ void mm(uint32_t sa, uint32_t sb,
                                   float acc[2][8][4], int lane, int mo, int no) {
#pragma unroll
    for (int kk = 0; kk < 8; kk++) {
        uint32_t a[2][4], b[4][4];
#pragma unroll
        for (int mt = 0; mt < 2; mt++) {
            if (!ATR) {
                ldm4(sa + swz(mo + mt * 16 + (lane & 15), kk * 2 + (lane >> 4)), a[mt]);
            } else {
                ldm4t(sa + swz(kk * 16 + ((lane >> 4) << 3) + (lane & 7),
                               ((mo + mt * 16) >> 3) + ((lane >> 3) & 1)), a[mt]);
            }
        }
#pragma unroll
        for (int nt2 = 0; nt2 < 4; nt2++) {
            if (!BTR) {
                ldm4(sb + swz(no + nt2 * 16 + ((lane >> 4) << 3) + (lane & 7),
                              kk * 2 + ((lane >> 3) & 1)), b[nt2]);
            } else {
                ldm4t(sb + swz(kk * 16 + ((lane >> 3) & 1) * 8 + (lane & 7),
                               ((no + nt2 * 16) >> 3) + (lane >> 4)), b[nt2]);
            }
        }
#pragma unroll
        for (int mt = 0; mt < 2; mt++)
#pragma unroll
            for (int nt = 0; nt < 8; nt++)
                mma16816(acc[mt][nt], a[mt],
                         b[nt >> 1][(nt & 1) * 2], b[nt >> 1][(nt & 1) * 2 + 1]);
    }
}

__device__ __forceinline__ void zacc(float acc[2][8][4]) {
#pragma unroll
    for (int mt = 0; mt < 2; mt++)
#pragma unroll
        for (int nt = 0; nt < 8; nt++)
#pragma unroll
            for (int j = 0; j < 4; j++) acc[mt][nt][j] = 0.0f;
}

// accum (scaled) -> bf16 row-major gmem tile
__device__ __forceinline__ void store_bf16(float acc[2][8][4],
                                           __nv_bfloat16* __restrict__ dst,
                                           int lane, int mo, int no, float scale) {
    int g = lane >> 2, t = lane & 3;
#pragma unroll
    for (int mt = 0; mt < 2; mt++)
#pragma unroll
        for (int nt = 0; nt < 8; nt++) {
            int col = no + nt * 8 + 2 * t;
            int r0 = mo + mt * 16 + g;
            *(uint32_t*)(dst + r0 * 128 + col) =
                pack_bf16(acc[mt][nt][0] * scale, acc[mt][nt][1] * scale);
            *(uint32_t*)(dst + (r0 + 8) * 128 + col) =
                pack_bf16(acc[mt][nt][2] * scale, acc[mt][nt][3] * scale);
        }
}

// accum -> bf16 swizzled smem tile
__device__ __forceinline__ void store_sw(float acc[2][8][4], char* buf,
                                         int lane, int mo, int no) {
    int g = lane >> 2, t = lane & 3;
#pragma unroll
    for (int mt = 0; mt < 2; mt++)
#pragma unroll
        for (int nt = 0; nt < 8; nt++) {
            int col = no + nt * 8 + 2 * t;
            int r0 = mo + mt * 16 + g, r1 = r0 + 8;
            *(uint32_t*)(buf + swz(r0, col >> 3) + (col & 7) * 2) =
                pack_bf16(acc[mt][nt][0], acc[mt][nt][1]);
            *(uint32_t*)(buf + swz(r1, col >> 3) + (col & 7) * 2) =
                pack_bf16(acc[mt][nt][2], acc[mt][nt][3]);
        }
}

// per-thread bf16 stash of accumulator to plain row-major smem (own slots only)
__device__ __forceinline__ void stash_store(float acc[2][8][4], char* buf,
                                            int lane, int mo, int no) {
    int g = lane >> 2, t = lane & 3;
#pragma unroll
    for (int mt = 0; mt < 2; mt++)
#pragma unroll
        for (int nt = 0; nt < 8; nt++) {
            int col = no + nt * 8 + 2 * t;
            int r0 = mo + mt * 16 + g, r1 = r0 + 8;
            *(uint32_t*)(buf + (r0 * 128 + col) * 2) = pack_bf16(acc[mt][nt][0], acc[mt][nt][1]);
            *(uint32_t*)(buf + (r1 * 128 + col) * 2) = pack_bf16(acc[mt][nt][2], acc[mt][nt][3]);
        }
}
__device__ __forceinline__ void stash_add(float acc[2][8][4], const char* buf,
                                          int lane, int mo, int no) {
    int g = lane >> 2, t = lane & 3;
#pragma unroll
    for (int mt = 0; mt < 2; mt++)
#pragma unroll
        for (int nt = 0; nt < 8; nt++) {
            int col = no + nt * 8 + 2 * t;
            int r0 = mo + mt * 16 + g, r1 = r0 + 8;
            uint32_t w0 = *(const uint32_t*)(buf + (r0 * 128 + col) * 2);
            uint32_t w1 = *(const uint32_t*)(buf + (r1 * 128 + col) * 2);
            __nv_bfloat162 h0 = *reinterpret_cast<__nv_bfloat162*>(&w0);
            __nv_bfloat162 h1 = *reinterpret_cast<__nv_bfloat162*>(&w1);
            acc[mt][nt][0] += __bfloat162float(h0.x);
            acc[mt][nt][1] += __bfloat162float(h0.y);
            acc[mt][nt][2] += __bfloat162float(h1.x);
            acc[mt][nt][3] += __bfloat162float(h1.y);
        }
}

// ===========================================================================
// Kernel 0: weights fp32 -> bf16 row-major gmem (one-shot, tiny)
// ===========================================================================
extern "C" __global__ void __launch_bounds__(256)
k_prep(const float* __restrict__ Wq, const float* __restrict__ Wk,
       const float* __restrict__ Wv, const float* __restrict__ Wo) {
    const float* srcs[4] = {Wq, Wk, Wv, Wo};
    int w = blockIdx.x >> 3, part = blockIdx.x & 7;
    const float4* s = (const float4*)(srcs[w] + part * 2048);
    uint32_t* d = (uint32_t*)(g_Wb + (size_t)w * TILE + part * 2048);
    int tid = threadIdx.x;
#pragma unroll
    for (int i = 0; i < 2; i++) {
        int idx = tid + i * 256;
        float4 v = s[idx];
        d[idx * 2]     = pack_bf16(v.x, v.y);
        d[idx * 2 + 1] = pack_bf16(v.z, v.w);
    }
}

// ===========================================================================
// Kernel 0b: G = Wq^T Wk / sqrt(H)  (CTA 0) ;  W2 = Wo @ Wv  (CTA 1)
// ===========================================================================
#define KP2_SMEM (2 * 32768)

extern "C" __global__ void __launch_bounds__(256, 1)
k_prep2() {
    extern __shared__ char smem[];
    char* a = smem;
    char* b = smem + 32768;
    int tid = threadIdx.x, wid = tid >> 5, lane = tid & 31;
    int mo = (wid & 3) * 32, no = (wid >> 2) * 64;
    uint32_t sa = smem_u32(a), sb = smem_u32(b);
    float acc[2][8][4];

    if (blockIdx.x == 0) {
        cp_tile(sa, g_Wb, tid);             // Wq
        cp_tile(sb, g_Wb + TILE, tid);      // Wk
        CP_COMMIT(); CP_WAIT();
        __syncthreads();
        zacc(acc);
        mm<1, 1>(sa, sb, acc, lane, mo, no);   // G[t1][t2] = sum_h Wq[h][t1] Wk[h][t2]
        store_bf16(acc, g_G, lane, mo, no, RSQRT_H);
    } else {
        cp_tile(sa, g_Wb + 3 * TILE, tid);  // Wo
        cp_tile(sb, g_Wb + 2 * TILE, tid);  // Wv
        CP_COMMIT(); CP_WAIT();
        __syncthreads();
        zacc(acc);
        mm<0, 1>(sa, sb, acc, lane, mo, no);   // W2[o][t] = sum_v Wo[o][v] Wv[v][t]
        store_bf16(acc, g_W2, lane, mo, no, 1.0f);
    }
}

// ===========================================================================
// Fused persistent kernel. smem: b0 / b1 / b2 (3 x 32KB).
//  b0 = Tn (resident A->C) -> proj stage
//  b1 = G -> U -> P -> Z
//  b2 = Tpre -> Z2 stash -> W2
// ===========================================================================
#define KF_SMEM (3 * 32768)

extern "C" __global__ void __launch_bounds__(256, 2)
k_fused(const float* __restrict__ tokens,
        const float* __restrict__ g1, const float* __restrict__ b1v,
        const float* __restrict__ g2, const float* __restrict__ b2v,
        float* __restrict__ out) {
    extern __shared__ char smem[];
    char* b0 = smem;
    char* b1 = smem + 32768;
    char* b2 = smem + 65536;
    int tid = threadIdx.x, wid = tid >> 5, lane = tid & 31;
    int mo = (wid & 3) * 32, no = (wid >> 2) * 64;
    int g = lane >> 2, t = lane & 3;
    int cid = blockIdx.x, base = cid * CH;
    uint32_t sb0 = smem_u32(b0), sb1 = smem_u32(b1), sb2 = smem_u32(b2);

    float acc[2][8][4];

    // ============================ PHASE A ==================================
    cp_tile(sb1, g_G, tid);                 // G prefetch (ready by phase C)
    CP_COMMIT();

    for (int r = wid; r < CH; r += 8) {
        float4 v = ((const float4*)(tokens + (size_t)(base + r) * 128))[lane];
        float s  = v.x + v.y + v.z + v.w;
        float s2 = v.x * v.x + v.y * v.y + v.z * v.z + v.w * v.w;
#pragma unroll
        for (int o = 16; o; o >>= 1) {
            s  += __shfl_xor_sync(0xffffffffu, s, o);
            s2 += __shfl_xor_sync(0xffffffffu, s2, o);
        }
        float mu  = s * (1.0f / 128.0f);
        float var = fmaxf(s2 * (1.0f / 128.0f) - mu * mu, 0.0f);
        float inv = rsqrtf(var + 1e-5f);
        float4 gg = ((const float4*)g1)[lane];
        float4 bb = ((const float4*)b1v)[lane];
        float o0 = (v.x - mu) * inv * gg.x + bb.x;
        float o1 = (v.y - mu) * inv * gg.y + bb.y;
        float o2 = (v.z - mu) * inv * gg.z + bb.z;
        float o3 = (v.w - mu) * inv * gg.w + bb.w;
        uint32_t off = swz(r, lane >> 1) + (lane & 1) * 8;
        *(uint32_t*)(b0 + off)     = pack_bf16(o0, o1);
        *(uint32_t*)(b0 + off + 4) = pack_bf16(o2, o3);
    }
    CP_WAIT();
    __syncthreads();

    // T = Tn^T @ Tn -> g_S
    zacc(acc);
    mm<1, 1>(sb0, sb0, acc, lane, mo, no);
    store_bf16(acc, g_S + (size_t)cid * TILE, lane, mo, no, 1.0f);

    grid_bar();                             // all T visible

    // ============================ PHASE B ==================================
    {
        int tg = cid * 256 + tid;           // 65536 threads == elements
        int b = tg >> 14, e = tg & 16383;
        const __nv_bfloat16* S = g_S + (size_t)b * NCB * TILE + e;
        __nv_bfloat16* M = g_M + (size_t)b * NCB * TILE + e;
        float s = 0.0f;
#pragma unroll 8
        for (int c = 0; c < NCB; c++) {
            M[(size_t)c * TILE] = __float2bfloat16(s);
            s += __bfloat162float(S[(size_t)c * TILE]);
        }
    }

    grid_bar();                             // all Tpre visible

    // ============================ PHASE C ==================================
    // Tpre -> b2 overlapped with U = Tn @ G
    cp_tile(sb2, g_M + (size_t)cid * TILE, tid);
    CP_COMMIT();
    zacc(acc);
    mm<0, 1>(sb0, sb1, acc, lane, mo, no);  // U[i][t] = sum Tn[i][t1] G[t1][t]
    CP_WAIT();
    __syncthreads();                        // G dead, Tpre ready

    store_sw(acc, b1, lane, mo, no);        // U -> b1
    __syncthreads();

    // Z2 = U @ Tpre
    zacc(acc);
    mm<0, 1>(sb1, sb2, acc, lane, mo, no);
    __syncthreads();                        // Tpre dead
    stash_store(acc, b2, lane, mo, no);     // Z2 stash -> b2 (own slots)

    // scores = U @ Tn^T
    zacc(acc);
    mm<0, 0>(sb1, sb0, acc, lane, mo, no);
    __syncthreads();                        // U dead

    // masked P -> b1
#pragma unroll
    for (int mt = 0; mt < 2; mt++)
#pragma unroll
        for (int nt = 0; nt < 8; nt++) {
            int col = no + nt * 8 + 2 * t;
            int r0 = mo + mt * 16 + g, r1 = r0 + 8;
            float v0 = (col     <= r0) ? acc[mt][nt][0] : 0.0f;
            float v1 = (col + 1 <= r0) ? acc[mt][nt][1] : 0.0f;
            float v2 = (col     <= r1) ? acc[mt][nt][2] : 0.0f;
            float v3 = (col + 1 <= r1) ? acc[mt][nt][3] : 0.0f;
            *(uint32_t*)(b1 + swz(r0, col >> 3) + (col & 7) * 2) = pack_bf16(v0, v1);
            *(uint32_t*)(b1 + swz(r1, col >> 3) + (col & 7) * 2) = pack_bf16(v2, v3);
        }
    __syncthreads();                        // P visible

    // Z = P @ Tn + Z2(stash)
    zacc(acc);
    mm<0, 1>(sb1, sb0, acc, lane, mo, no);
    stash_add(acc, b2, lane, mo, no);
    __syncthreads();                        // P dead, stash consumed

    // Z -> b1 ; W2 -> b2
    store_sw(acc, b1, lane, mo, no);
    cp_tile(sb2, g_W2, tid);
    CP_COMMIT(); CP_WAIT();
    __syncthreads();

    // proj = Z @ W2^T
    zacc(acc);
    mm<0, 0>(sb1, sb2, acc, lane, mo, no);
    __syncthreads();                        // Tn (b0) dead

    // 0.1*proj -> b0 bf16 row-major
#pragma unroll
    for (int mt = 0; mt < 2; mt++)
#pragma unroll
        for (int nt = 0; nt < 8; nt++) {
            int col = no + nt * 8 + 2 * t;
            int r0 = mo + mt * 16 + g, r1 = r0 + 8;
            *(uint32_t*)(b0 + (r0 * 128 + col) * 2) =
                pack_bf16(0.1f * acc[mt][nt][0], 0.1f * acc[mt][nt][1]);
            *(uint32_t*)(b0 + (r1 * 128 + col) * 2) =
                pack_bf16(0.1f * acc[mt][nt][2], 0.1f * acc[mt][nt][3]);
        }
    __syncthreads();

    // LN2(tokens + res) -> out
    for (int r = wid; r < CH; r += 8) {
        float4 tv = ((const float4*)(tokens + (size_t)(base + r) * 128))[lane];
        uint2 pr = *(const uint2*)(b0 + (r * 128 + lane * 4) * 2);
        __nv_bfloat162 p0 = *reinterpret_cast<__nv_bfloat162*>(&pr.x);
        __nv_bfloat162 p1 = *reinterpret_cast<__nv_bfloat162*>(&pr.y);
        float x0 = tv.x + __bfloat162float(p0.x);
        float x1 = tv.y + __bfloat162float(p0.y);
        float x2 = tv.z + __bfloat162float(p1.x);
        float x3 = tv.w + __bfloat162float(p1.y);
        float s  = x0 + x1 + x2 + x3;
        float s2 = x0 * x0 + x1 * x1 + x2 * x2 + x3 * x3;
#pragma unroll
        for (int o = 16; o; o >>= 1) {
            s  += __shfl_xor_sync(0xffffffffu, s, o);
            s2 += __shfl_xor_sync(0xffffffffu, s2, o);
        }
        float mu  = s * (1.0f / 128.0f);
        float var = fmaxf(s2 * (1.0f / 128.0f) - mu * mu, 0.0f);
        float inv = rsqrtf(var + 1e-5f);
        float4 gg = ((const float4*)g2)[lane];
        float4 bb = ((const float4*)b2v)[lane];
        float4 o4;
        o4.x = (x0 - mu) * inv * gg.x + bb.x;
        o4.y = (x1 - mu) * inv * gg.y + bb.y;
        o4.z = (x2 - mu) * inv * gg.z + bb.z;
        o4.w = (x3 - mu) * inv * gg.w + bb.w;
        ((float4*)(out + (size_t)(base + r) * 128))[lane] = o4;
    }
}

// ===========================================================================
extern "C" void kernel_launch(void* const* d_in, const int* in_sizes, int n_in,
                              void* d_out, int out_size) {
    const float* tokens = (const float*)d_in[0];
    const float* Wq = (const float*)d_in[1];
    const float* Wk = (const float*)d_in[2];
    const float* Wv = (const float*)d_in[3];
    const float* Wo = (const float*)d_in[4];
    const float* g1 = (const float*)d_in[5];
    const float* b1 = (const float*)d_in[6];
    const float* g2 = (const float*)d_in[7];
    const float* b2 = (const float*)d_in[8];
    float* out = (float*)d_out;

    cudaFuncSetAttribute(k_prep2, cudaFuncAttributeMaxDynamicSharedMemorySize, KP2_SMEM);
    cudaFuncSetAttribute(k_fused, cudaFuncAttributeMaxDynamicSharedMemorySize, KF_SMEM);

    k_prep<<<32, 256>>>(Wq, Wk, Wv, Wo);
    k_prep2<<<2, 256, KP2_SMEM>>>();
    k_fused<<<NCHUNK, 256, KF_SMEM>>>(tokens, g1, b1, g2, b2, out);
}